// round 1
// baseline (speedup 1.0000x reference)
#include <cuda_runtime.h>

// ---------------- problem constants ----------------
#define BB 16
#define HH 56
#define WW 56
#define LL (HH*WW)      // 3136
#define DD 128
#define KK 4

#define LOG2E 1.4426950408889634f
#define LN2   0.6931471805599453f

// ---------------- scratch (device globals; no allocs allowed) ----------------
__device__ float g_xz  [(size_t)BB*LL*256];     // in_proj output (xi | z), channel-last
__device__ float g_xc  [(size_t)BB*LL*DD];      // conv+silu output, channel-last
__device__ float g_proj[(size_t)BB*LL*24];      // x_dbl: per spatial pos, [k*6 + c]
__device__ float g_dA  [(size_t)BB*KK*LL*DD];   // scan-ordered [b][k][l][d]
__device__ float g_dBu [(size_t)BB*KK*LL*DD];   // scan-ordered
__device__ float g_y   [(size_t)BB*KK*LL*DD];   // scan output, scan-ordered
__device__ float g_C   [(size_t)BB*KK*LL];      // C gate, scan-ordered

// ---------------- math helpers (MUFU) ----------------
__device__ __forceinline__ float ex2f(float x){ float y; asm("ex2.approx.ftz.f32 %0,%1;" : "=f"(y) : "f"(x)); return y; }
__device__ __forceinline__ float lg2f(float x){ float y; asm("lg2.approx.ftz.f32 %0,%1;" : "=f"(y) : "f"(x)); return y; }
__device__ __forceinline__ float rcpf(float x){ float y; asm("rcp.approx.ftz.f32 %0,%1;" : "=f"(y) : "f"(x)); return y; }
__device__ __forceinline__ float fsigmoid(float x){ return rcpf(1.f + ex2f(-x*LOG2E)); }

// ---------------- K0: zero d_out ----------------
__global__ void k_zero(float* out){
    int i = blockIdx.x*blockDim.x + threadIdx.x;
    if (i < BB*DD) out[i] = 0.f;
}

// ---------------- K1: in_proj GEMM  (M=50176,N=256,K=128) ----------------
// out[m,n] = sum_k X[m,k] * Wm[n,k]
__global__ void k_gemm(const float* __restrict__ X, const float* __restrict__ Wm){
    __shared__ float As[32][64];
    __shared__ float Ws[32][64];
    const int row0 = blockIdx.x * 64;
    const int col0 = blockIdx.y * 64;
    const int t = threadIdx.x;              // 256 threads
    const int tx = t & 15, ty = t >> 4;     // 16x16
    float c[4][4] = {};
    #pragma unroll
    for (int kb = 0; kb < 128; kb += 32){
        #pragma unroll
        for (int i = t; i < 512; i += 256){           // 64 rows * 8 float4
            int m  = i >> 3;
            int k4 = (i & 7) << 2;
            float4 v = *(const float4*)&X[(size_t)(row0+m)*128 + kb + k4];
            As[k4+0][m]=v.x; As[k4+1][m]=v.y; As[k4+2][m]=v.z; As[k4+3][m]=v.w;
        }
        #pragma unroll
        for (int i = t; i < 512; i += 256){
            int n  = i >> 3;
            int k4 = (i & 7) << 2;
            float4 v = *(const float4*)&Wm[(size_t)(col0+n)*128 + kb + k4];
            Ws[k4+0][n]=v.x; Ws[k4+1][n]=v.y; Ws[k4+2][n]=v.z; Ws[k4+3][n]=v.w;
        }
        __syncthreads();
        #pragma unroll
        for (int kk = 0; kk < 32; kk++){
            float4 a = *(const float4*)&As[kk][tx*4];
            float4 b = *(const float4*)&Ws[kk][ty*4];
            float av[4] = {a.x,a.y,a.z,a.w};
            float bv[4] = {b.x,b.y,b.z,b.w};
            #pragma unroll
            for (int i=0;i<4;i++)
                #pragma unroll
                for (int j=0;j<4;j++)
                    c[i][j] = fmaf(av[i], bv[j], c[i][j]);
        }
        __syncthreads();
    }
    #pragma unroll
    for (int i=0;i<4;i++){
        float4 v = make_float4(c[i][0],c[i][1],c[i][2],c[i][3]);
        *(float4*)&g_xz[(size_t)(row0 + tx*4 + i)*256 + col0 + ty*4] = v;
    }
}

// ---------------- K2: depthwise 3x3 conv + bias + SiLU ----------------
__global__ void k_conv(const float* __restrict__ cw, const float* __restrict__ cb){
    __shared__ float wsh[DD*9];
    __shared__ float bsh[DD];
    const int t = threadIdx.x;   // 256
    for (int i = t; i < DD*9; i += 256) wsh[i] = cw[i];
    if (t < DD) bsh[t] = cb[t];
    __syncthreads();
    int idx = blockIdx.x*256 + t;           // over B*L*D
    int d = idx & 127;
    int rest = idx >> 7;
    int w = rest % WW; rest /= WW;
    int h = rest % HH;
    int b = rest / HH;
    float s = bsh[d];
    const float* wp = &wsh[d*9];
    #pragma unroll
    for (int dy = -1; dy <= 1; dy++){
        int hh = h + dy;
        bool okh = (hh >= 0) && (hh < HH);
        #pragma unroll
        for (int dx = -1; dx <= 1; dx++){
            int ww = w + dx;
            if (okh && ww >= 0 && ww < WW){
                s = fmaf(g_xz[((size_t)(b*LL + hh*WW + ww))*256 + d],
                         wp[(dy+1)*3 + (dx+1)], s);
            }
        }
    }
    float sil = s * fsigmoid(s);
    g_xc[((size_t)(b*LL + h*WW + w))*128 + d] = sil;
}

// ---------------- K3: x_dbl projection (24 x 128 per position) ----------------
__global__ void k_xdbl(const float* __restrict__ xpw){
    __shared__ float wp[24][129];
    __shared__ float xr[8][129];
    const int t = threadIdx.x;   // 192
    for (int i = t; i < 24*128; i += 192) wp[i>>7][i&127] = xpw[i];
    const int pos0 = blockIdx.x * 8;   // linear over B*L
    for (int i = t; i < 8*128; i += 192) xr[i>>7][i&127] = g_xc[(size_t)pos0*128 + i];
    __syncthreads();
    const int pos = t / 24;
    const int c   = t - pos*24;
    float acc = 0.f;
    #pragma unroll 8
    for (int i = 0; i < 128; i++) acc = fmaf(xr[pos][i], wp[c][i], acc);
    g_proj[(size_t)(pos0 + pos)*24 + c] = acc;
}

// ---------------- K4: dt/softplus/dA/dBu precompute, written in scan order ----------------
__global__ void k_dt(const float* __restrict__ dtw, const float* __restrict__ dtb,
                     const float* __restrict__ alog){
    const int bp = blockIdx.x;          // 0 .. B*L-1
    const int d  = threadIdx.x;         // 128
    const int b = bp / LL, p = bp - b*LL;
    const int h = p / WW, w = p - h*WW;
    const int lw = w*HH + h;            // column-major scan index
    const float xcv = g_xc[(size_t)bp*128 + d];
    const float* pr = &g_proj[(size_t)bp*24];
    #pragma unroll
    for (int k = 0; k < 4; k++){
        float4 wv = *(const float4*)&dtw[(size_t)(k*128 + d)*4];
        float p0 = pr[k*6+0], p1 = pr[k*6+1], p2 = pr[k*6+2], p3 = pr[k*6+3];
        float Bv = pr[k*6+4], Cv = pr[k*6+5];
        float xdt = dtb[k*128 + d];
        xdt = fmaf(wv.x, p0, xdt);
        xdt = fmaf(wv.y, p1, xdt);
        xdt = fmaf(wv.z, p2, xdt);
        xdt = fmaf(wv.w, p3, xdt);
        // softplus via base-2: u = log2(1 + 2^(x*log2e));  dt = u*ln2;  dA = 2^(A*u)
        float tt = ex2f(fminf(xdt, 20.f) * LOG2E);
        float u  = (xdt > 20.f) ? xdt * LOG2E : lg2f(1.f + tt);
        float dtv = u * LN2;
        float Aval = -ex2f(alog[k*128 + d] * LOG2E);   // A = -exp(A_log)
        float dAv  = ex2f(Aval * u);                   // exp(A*dt)
        float dBuv = dtv * Bv * xcv;
        int l = (k==0) ? p : (k==1) ? (LL-1-p) : (k==2) ? lw : (LL-1-lw);
        size_t base = (((size_t)(b*4 + k))*LL + l)*128 + d;
        g_dA[base]  = dAv;
        g_dBu[base] = dBuv;
        if (d == 0) g_C[(size_t)(b*4 + k)*LL + l] = Cv;
    }
}

// ---------------- K5: selective scan (scalar state, N=1) ----------------
__global__ void k_scan(){
    const int g = blockIdx.x;     // b*4 + k, 64 groups
    const int d = threadIdx.x;    // 128
    size_t base = (size_t)g * LL * 128 + d;
    const float* Cp = &g_C[(size_t)g * LL];
    float h = 0.f;
    #pragma unroll 4
    for (int l = 0; l < LL; l++){
        float da = g_dA [base + (size_t)l*128];
        float db = g_dBu[base + (size_t)l*128];
        h = fmaf(da, h, db);
        g_y[base + (size_t)l*128] = h * Cp[l];
    }
}

// ---------------- K6: direction merge + LayerNorm + SiLU gate + spatial mean ----------------
__global__ void k_final(const float* __restrict__ Ds, const float* __restrict__ nw,
                        const float* __restrict__ nb, float* __restrict__ out){
    const int b = blockIdx.y;
    const int h = blockIdx.x;
    const int d = threadIdx.x;         // 128
    const int warp = d >> 5, lane = d & 31;
    __shared__ float red[4];
    const float sumDs = Ds[d] + Ds[128+d] + Ds[256+d] + Ds[384+d];
    const float w_n = nw[d], b_n = nb[d];
    float acc = 0.f;
    const size_t bL = (size_t)b * 4 * LL;
    for (int w = 0; w < WW; w++){
        int p  = h*WW + w;
        int lw = w*HH + h;
        float v = g_y[(bL +            p )*128 + d]
                + g_y[(bL +   LL + (LL-1-p ))*128 + d]
                + g_y[(bL + 2*LL +       lw )*128 + d]
                + g_y[(bL + 3*LL + (LL-1-lw))*128 + d]
                + g_xc[((size_t)b*LL + p)*128 + d] * sumDs;
        // mean over channels
        float s = v;
        #pragma unroll
        for (int o = 16; o > 0; o >>= 1) s += __shfl_xor_sync(~0u, s, o);
        if (lane == 0) red[warp] = s;
        __syncthreads();
        float mu = (red[0]+red[1]+red[2]+red[3]) * (1.f/128.f);
        __syncthreads();
        float dv = v - mu;
        float s2 = dv * dv;
        #pragma unroll
        for (int o = 16; o > 0; o >>= 1) s2 += __shfl_xor_sync(~0u, s2, o);
        if (lane == 0) red[warp] = s2;
        __syncthreads();
        float var = (red[0]+red[1]+red[2]+red[3]) * (1.f/128.f);
        __syncthreads();
        float yn = dv * rsqrtf(var + 1e-5f) * w_n + b_n;
        float z  = g_xz[((size_t)(b*LL + p))*256 + 128 + d];
        acc = fmaf(yn, z * fsigmoid(z), acc);
    }
    atomicAdd(&out[b*128 + d], acc * (1.f/(float)LL));
}

// ---------------- launch ----------------
extern "C" void kernel_launch(void* const* d_in, const int* in_sizes, int n_in,
                              void* d_out, int out_size){
    const float* x    = (const float*)d_in[0];
    const float* inw  = (const float*)d_in[1];
    const float* cw   = (const float*)d_in[2];
    const float* cb   = (const float*)d_in[3];
    const float* xpw  = (const float*)d_in[4];
    const float* dtw  = (const float*)d_in[5];
    const float* dtb  = (const float*)d_in[6];
    const float* alog = (const float*)d_in[7];
    const float* Ds   = (const float*)d_in[8];
    const float* onw  = (const float*)d_in[9];
    const float* onb  = (const float*)d_in[10];
    float* out = (float*)d_out;

    k_zero<<<(BB*DD + 255)/256, 256>>>(out);
    k_gemm<<<dim3((BB*LL)/64, 256/64), 256>>>(x, inw);
    k_conv<<<(BB*LL*DD)/256, 256>>>(cw, cb);
    k_xdbl<<<(BB*LL)/8, 192>>>(xpw);
    k_dt<<<BB*LL, 128>>>(dtw, dtb, alog);
    k_scan<<<BB*KK, 128>>>();
    k_final<<<dim3(HH, BB), 128>>>(Ds, onw, onb, out);
}

// round 2
// speedup vs baseline: 5.6511x; 5.6511x over previous
#include <cuda_runtime.h>

// ---------------- problem constants ----------------
#define BB 16
#define HH 56
#define WW 56
#define LL (HH*WW)      // 3136
#define DD 128
#define KK 4
#define NSEG 28
#define SEGLEN 112      // 28*112 = 3136

#define LOG2E 1.4426950408889634f
#define LN2   0.6931471805599453f

// ---------------- scratch (device globals; no allocs allowed) ----------------
__device__ float g_xz   [(size_t)BB*LL*256];     // in_proj output (xi | z), channel-last
__device__ float g_xc   [(size_t)BB*LL*DD];      // conv+silu output, channel-last
__device__ float g_proj [(size_t)BB*LL*24];      // x_dbl: per spatial pos, [k*6 + c]
__device__ float g_y    [(size_t)KK*BB*LL*DD];   // scan output, SPATIAL order per direction
__device__ float g_hend [(size_t)64*NSEG*DD];
__device__ float g_aprod[(size_t)64*NSEG*DD];
__device__ float g_init [(size_t)64*NSEG*DD];

// ---------------- math helpers (MUFU) ----------------
__device__ __forceinline__ float ex2f(float x){ float y; asm("ex2.approx.ftz.f32 %0,%1;" : "=f"(y) : "f"(x)); return y; }
__device__ __forceinline__ float lg2f(float x){ float y; asm("lg2.approx.ftz.f32 %0,%1;" : "=f"(y) : "f"(x)); return y; }
__device__ __forceinline__ float rcpf(float x){ float y; asm("rcp.approx.ftz.f32 %0,%1;" : "=f"(y) : "f"(x)); return y; }
__device__ __forceinline__ float fsigmoid(float x){ return rcpf(1.f + ex2f(-x*LOG2E)); }

// ---------------- K0: zero d_out ----------------
__global__ void k_zero(float* out){
    int i = blockIdx.x*blockDim.x + threadIdx.x;
    if (i < BB*DD) out[i] = 0.f;
}

// ---------------- K1: in_proj GEMM (M=50176, N=256, K=128), 128x128 tile ----------------
__global__ void __launch_bounds__(256,2) k_gemm(const float* __restrict__ X, const float* __restrict__ Wm){
    __shared__ float As[32][132];
    __shared__ float Bs[32][132];
    const int row0 = blockIdx.x * 128;
    const int col0 = blockIdx.y * 128;
    const int t = threadIdx.x;
    const int tx = t & 15;      // n-group
    const int ty = t >> 4;      // m-group
    float c[8][8] = {};
    #pragma unroll
    for (int kb = 0; kb < 128; kb += 32){
        #pragma unroll
        for (int j = 0; j < 4; j++){
            int i = t + j*256;
            int r  = i >> 3;
            int kq = (i & 7) << 2;
            float4 v = *(const float4*)&X[(size_t)(row0+r)*128 + kb + kq];
            As[kq+0][r]=v.x; As[kq+1][r]=v.y; As[kq+2][r]=v.z; As[kq+3][r]=v.w;
        }
        #pragma unroll
        for (int j = 0; j < 4; j++){
            int i = t + j*256;
            int r  = i >> 3;
            int kq = (i & 7) << 2;
            float4 v = *(const float4*)&Wm[(size_t)(col0+r)*128 + kb + kq];
            Bs[kq+0][r]=v.x; Bs[kq+1][r]=v.y; Bs[kq+2][r]=v.z; Bs[kq+3][r]=v.w;
        }
        __syncthreads();
        #pragma unroll
        for (int kk = 0; kk < 32; kk++){
            float a[8], b[8];
            *(float4*)&a[0] = *(const float4*)&As[kk][ty*8];
            *(float4*)&a[4] = *(const float4*)&As[kk][ty*8+4];
            *(float4*)&b[0] = *(const float4*)&Bs[kk][tx*8];
            *(float4*)&b[4] = *(const float4*)&Bs[kk][tx*8+4];
            #pragma unroll
            for (int i=0;i<8;i++)
                #pragma unroll
                for (int j=0;j<8;j++)
                    c[i][j] = fmaf(a[i], b[j], c[i][j]);
        }
        __syncthreads();
    }
    #pragma unroll
    for (int i=0;i<8;i++){
        size_t ro = (size_t)(row0 + ty*8 + i)*256 + col0 + tx*8;
        *(float4*)&g_xz[ro]   = make_float4(c[i][0],c[i][1],c[i][2],c[i][3]);
        *(float4*)&g_xz[ro+4] = make_float4(c[i][4],c[i][5],c[i][6],c[i][7]);
    }
}

// ---------------- K2: depthwise 3x3 conv + bias + SiLU (float4 over d) ----------------
__global__ void k_conv(const float* __restrict__ cw, const float* __restrict__ cb){
    __shared__ float wsh[9][128];
    __shared__ float bsh[128];
    const int t = threadIdx.x;   // 256
    for (int i = t; i < 1152; i += 256) wsh[i % 9][i / 9] = cw[i];
    if (t < 128) bsh[t] = cb[t];
    __syncthreads();
    int idx = blockIdx.x*256 + t;        // over B*L*32 (channel quads)
    int dq = idx & 31;
    int rest = idx >> 5;
    int w = rest % WW; rest /= WW;
    int h = rest % HH;
    int b = rest / HH;
    float4 wv[9];
    #pragma unroll
    for (int tap = 0; tap < 9; tap++) wv[tap] = *(const float4*)&wsh[tap][dq*4];
    float4 s = *(const float4*)&bsh[dq*4];
    #pragma unroll
    for (int dy = -1; dy <= 1; dy++){
        int hh = h + dy;
        bool okh = (hh >= 0) && (hh < HH);
        #pragma unroll
        for (int dx = -1; dx <= 1; dx++){
            int ww = w + dx;
            if (okh && ww >= 0 && ww < WW){
                float4 xv = *(const float4*)&g_xz[((size_t)(b*LL + hh*WW + ww))*256 + dq*4];
                float4 wt = wv[(dy+1)*3 + (dx+1)];
                s.x = fmaf(xv.x, wt.x, s.x);
                s.y = fmaf(xv.y, wt.y, s.y);
                s.z = fmaf(xv.z, wt.z, s.z);
                s.w = fmaf(xv.w, wt.w, s.w);
            }
        }
    }
    s.x *= fsigmoid(s.x); s.y *= fsigmoid(s.y); s.z *= fsigmoid(s.z); s.w *= fsigmoid(s.w);
    *(float4*)&g_xc[((size_t)(b*LL + h*WW + w))*128 + dq*4] = s;
}

// ---------------- K3: x_dbl projection (24 outputs x 128-dot per position) ----------------
__global__ void k_xdbl(const float* __restrict__ xpw){
    __shared__ float wp[24][132];
    __shared__ float xr[8][132];
    const int t = threadIdx.x;   // 192
    for (int i = t; i < 24*128; i += 192) wp[i>>7][i&127] = xpw[i];
    const int pos0 = blockIdx.x * 8;   // linear over B*L
    const float4* xcp = (const float4*)&g_xc[(size_t)pos0*128];
    for (int i = t; i < 256; i += 192) *(float4*)&xr[i>>5][(i&31)*4] = xcp[i];
    __syncthreads();
    const int pos = t / 24;
    const int c   = t - pos*24;
    float acc = 0.f;
    #pragma unroll
    for (int i4 = 0; i4 < 32; i4++){
        float4 xv = *(const float4*)&xr[pos][i4*4];
        float4 wv = *(const float4*)&wp[c][i4*4];
        acc = fmaf(xv.x, wv.x, acc);
        acc = fmaf(xv.y, wv.y, acc);
        acc = fmaf(xv.z, wv.z, acc);
        acc = fmaf(xv.w, wv.w, acc);
    }
    g_proj[(size_t)(pos0 + pos)*24 + c] = acc;
}

// ---------------- scan body (dA/dBu recomputed on the fly) ----------------
template<int KD, bool P2>
__device__ __forceinline__ void scan_seg(int g, int b, int seg, int d,
                                         float4 wv, float bias, float Aval, float hinit){
    int l0 = seg*SEGLEN;
    int p, h_, w_;
    if      (KD == 0){ p = l0; }
    else if (KD == 1){ p = LL-1-l0; }
    else if (KD == 2){ w_ = l0/HH; h_ = l0 - w_*HH; p = h_*WW + w_; }
    else             { int lw = LL-1-l0; w_ = lw/HH; h_ = lw - w_*HH; p = h_*WW + w_; }
    float hst = hinit, ap = 1.f;
    #pragma unroll 4
    for (int i = 0; i < SEGLEN; i++){
        const float* pr = &g_proj[((size_t)(b*LL + p))*24 + KD*6];
        float xcv = g_xc[((size_t)(b*LL + p))*128 + d];
        float p0 = __ldg(pr+0), p1 = __ldg(pr+1), p2 = __ldg(pr+2), p3 = __ldg(pr+3);
        float Bv = __ldg(pr+4), Cv = __ldg(pr+5);
        float xdt = fmaf(wv.x, p0, bias);
        xdt = fmaf(wv.y, p1, xdt);
        xdt = fmaf(wv.z, p2, xdt);
        xdt = fmaf(wv.w, p3, xdt);
        float tt = ex2f(fminf(xdt, 20.f) * LOG2E);
        float u  = (xdt > 20.f) ? xdt * LOG2E : lg2f(1.f + tt);
        float da = ex2f(Aval * u);
        float db = u * LN2 * Bv * xcv;
        hst = fmaf(da, hst, db);
        if (P2){
            g_y[(((size_t)(KD*BB + b))*LL + p)*128 + d] = hst * Cv;
        } else {
            ap *= da;
        }
        if      (KD == 0){ p++; }
        else if (KD == 1){ p--; }
        else if (KD == 2){ h_++; p += WW; if (h_ == HH){ h_ = 0; w_++; p = w_; } }
        else             { h_--; p -= WW; if (h_ <  0){ h_ = HH-1; w_--; p = (HH-1)*WW + w_; } }
    }
    if (!P2){
        size_t idx = ((size_t)g*NSEG + seg)*128 + d;
        g_hend[idx]  = hst;
        g_aprod[idx] = ap;
    }
}

// ---------------- K4: scan pass 1 (per-segment local scan) ----------------
__global__ void k_pass1(const float* __restrict__ dtw, const float* __restrict__ dtb,
                        const float* __restrict__ alog){
    const int g = blockIdx.x, seg = blockIdx.y, d = threadIdx.x;
    const int b = g >> 2, k = g & 3;
    float4 wv = *(const float4*)&dtw[(size_t)(k*128 + d)*4];
    float bias = dtb[k*128 + d];
    float Aval = -ex2f(alog[k*128 + d] * LOG2E);
    switch (k){
        case 0: scan_seg<0,false>(g,b,seg,d,wv,bias,Aval,0.f); break;
        case 1: scan_seg<1,false>(g,b,seg,d,wv,bias,Aval,0.f); break;
        case 2: scan_seg<2,false>(g,b,seg,d,wv,bias,Aval,0.f); break;
        default:scan_seg<3,false>(g,b,seg,d,wv,bias,Aval,0.f); break;
    }
}

// ---------------- K5: combine (prefix over segments) ----------------
__global__ void k_comb(){
    const int g = blockIdx.x, d = threadIdx.x;
    float carry = 0.f;
    for (int s = 0; s < NSEG; s++){
        size_t idx = ((size_t)g*NSEG + s)*128 + d;
        g_init[idx] = carry;
        carry = fmaf(g_aprod[idx], carry, g_hend[idx]);
    }
}

// ---------------- K6: scan pass 2 (replay with carry, write y in spatial order) ----------------
__global__ void k_pass2(const float* __restrict__ dtw, const float* __restrict__ dtb,
                        const float* __restrict__ alog){
    const int g = blockIdx.x, seg = blockIdx.y, d = threadIdx.x;
    const int b = g >> 2, k = g & 3;
    float4 wv = *(const float4*)&dtw[(size_t)(k*128 + d)*4];
    float bias = dtb[k*128 + d];
    float Aval = -ex2f(alog[k*128 + d] * LOG2E);
    float hinit = g_init[((size_t)g*NSEG + seg)*128 + d];
    switch (k){
        case 0: scan_seg<0,true>(g,b,seg,d,wv,bias,Aval,hinit); break;
        case 1: scan_seg<1,true>(g,b,seg,d,wv,bias,Aval,hinit); break;
        case 2: scan_seg<2,true>(g,b,seg,d,wv,bias,Aval,hinit); break;
        default:scan_seg<3,true>(g,b,seg,d,wv,bias,Aval,hinit); break;
    }
}

// ---------------- K7: direction merge + LayerNorm + SiLU gate + spatial mean ----------------
// warp-per-position, thread handles 4 channels (float4). No __syncthreads.
__global__ void k_final(const float* __restrict__ Ds, const float* __restrict__ nw,
                        const float* __restrict__ nb, float* __restrict__ out){
    const int b = blockIdx.y;
    const int t = threadIdx.x;        // 256
    const int warp = t >> 5, lane = t & 31;
    const int d4 = lane*4;
    const size_t SL = (size_t)BB*LL*128;   // direction slice stride

    float4 ds0 = *(const float4*)&Ds[d4];
    float4 ds1 = *(const float4*)&Ds[128 + d4];
    float4 ds2 = *(const float4*)&Ds[256 + d4];
    float4 ds3 = *(const float4*)&Ds[384 + d4];
    float4 sds = make_float4(ds0.x+ds1.x+ds2.x+ds3.x, ds0.y+ds1.y+ds2.y+ds3.y,
                             ds0.z+ds1.z+ds2.z+ds3.z, ds0.w+ds1.w+ds2.w+ds3.w);
    float4 w4 = *(const float4*)&nw[d4];
    float4 b4 = *(const float4*)&nb[d4];

    float4 acc = make_float4(0.f,0.f,0.f,0.f);
    #pragma unroll 2
    for (int j = 0; j < 8; j++){
        int p = blockIdx.x*64 + warp*8 + j;
        size_t base = ((size_t)(b*LL + p))*128 + d4;
        float4 y0 = *(const float4*)&g_y[base];
        float4 y1 = *(const float4*)&g_y[base + SL];
        float4 y2 = *(const float4*)&g_y[base + 2*SL];
        float4 y3 = *(const float4*)&g_y[base + 3*SL];
        float4 xc = *(const float4*)&g_xc[base];
        float4 v;
        v.x = y0.x+y1.x+y2.x+y3.x + xc.x*sds.x;
        v.y = y0.y+y1.y+y2.y+y3.y + xc.y*sds.y;
        v.z = y0.z+y1.z+y2.z+y3.z + xc.z*sds.z;
        v.w = y0.w+y1.w+y2.w+y3.w + xc.w*sds.w;
        float s = v.x+v.y+v.z+v.w;
        #pragma unroll
        for (int o = 16; o > 0; o >>= 1) s += __shfl_xor_sync(~0u, s, o);
        float mu = s * (1.f/128.f);
        float4 dv = make_float4(v.x-mu, v.y-mu, v.z-mu, v.w-mu);
        float s2 = dv.x*dv.x + dv.y*dv.y + dv.z*dv.z + dv.w*dv.w;
        #pragma unroll
        for (int o = 16; o > 0; o >>= 1) s2 += __shfl_xor_sync(~0u, s2, o);
        float rstd = rsqrtf(s2 * (1.f/128.f) + 1e-5f);
        float4 z = *(const float4*)&g_xz[((size_t)(b*LL + p))*256 + 128 + d4];
        float gx = z.x*fsigmoid(z.x), gy = z.y*fsigmoid(z.y);
        float gz = z.z*fsigmoid(z.z), gw = z.w*fsigmoid(z.w);
        acc.x = fmaf(fmaf(dv.x*rstd, w4.x, b4.x), gx, acc.x);
        acc.y = fmaf(fmaf(dv.y*rstd, w4.y, b4.y), gy, acc.y);
        acc.z = fmaf(fmaf(dv.z*rstd, w4.z, b4.z), gz, acc.z);
        acc.w = fmaf(fmaf(dv.w*rstd, w4.w, b4.w), gw, acc.w);
    }
    const float sc = 1.f/(float)LL;
    atomicAdd(&out[b*128 + d4 + 0], acc.x*sc);
    atomicAdd(&out[b*128 + d4 + 1], acc.y*sc);
    atomicAdd(&out[b*128 + d4 + 2], acc.z*sc);
    atomicAdd(&out[b*128 + d4 + 3], acc.w*sc);
}

// ---------------- launch ----------------
extern "C" void kernel_launch(void* const* d_in, const int* in_sizes, int n_in,
                              void* d_out, int out_size){
    const float* x    = (const float*)d_in[0];
    const float* inw  = (const float*)d_in[1];
    const float* cw   = (const float*)d_in[2];
    const float* cb   = (const float*)d_in[3];
    const float* xpw  = (const float*)d_in[4];
    const float* dtw  = (const float*)d_in[5];
    const float* dtb  = (const float*)d_in[6];
    const float* alog = (const float*)d_in[7];
    const float* Ds   = (const float*)d_in[8];
    const float* onw  = (const float*)d_in[9];
    const float* onb  = (const float*)d_in[10];
    float* out = (float*)d_out;

    k_zero<<<(BB*DD + 255)/256, 256>>>(out);
    k_gemm<<<dim3((BB*LL)/128, 2), 256>>>(x, inw);
    k_conv<<<(BB*LL*32)/256, 256>>>(cw, cb);
    k_xdbl<<<(BB*LL)/8, 192>>>(xpw);
    k_pass1<<<dim3(64, NSEG), 128>>>(dtw, dtb, alog);
    k_comb<<<64, 128>>>();
    k_pass2<<<dim3(64, NSEG), 128>>>(dtw, dtb, alog);
    k_final<<<dim3(LL/64, BB), 256>>>(Ds, onw, onb, out);
}

// round 3
// speedup vs baseline: 6.2839x; 1.1120x over previous
#include <cuda_runtime.h>

// ---------------- problem constants ----------------
#define BB 16
#define HH 56
#define WW 56
#define LL (HH*WW)      // 3136
#define DD 128
#define KK 4
#define NSEG 56
#define SEGLEN 56       // 56*56 = 3136

#define LOG2E 1.4426950408889634f
#define LN2   0.6931471805599453f

// ---------------- scratch (device globals; no allocs allowed) ----------------
__device__ float g_xz   [(size_t)BB*LL*256];     // in_proj output (xi | z), channel-last
__device__ float g_xc   [(size_t)BB*LL*DD];      // conv+silu output, channel-last
__device__ float g_proj [(size_t)BB*LL*24];      // x_dbl: per pos, [k*6 + c]
__device__ float g_ysum [(size_t)BB*LL*DD];      // fused 4-direction y + Ds*xc
__device__ float g_hend [(size_t)64*NSEG*DD];
__device__ float g_aprod[(size_t)64*NSEG*DD];
__device__ float g_init [(size_t)64*NSEG*DD];

// ---------------- math helpers (MUFU) ----------------
__device__ __forceinline__ float ex2f(float x){ float y; asm("ex2.approx.ftz.f32 %0,%1;" : "=f"(y) : "f"(x)); return y; }
__device__ __forceinline__ float lg2f(float x){ float y; asm("lg2.approx.ftz.f32 %0,%1;" : "=f"(y) : "f"(x)); return y; }
__device__ __forceinline__ float rcpf(float x){ float y; asm("rcp.approx.ftz.f32 %0,%1;" : "=f"(y) : "f"(x)); return y; }
__device__ __forceinline__ float fsigmoid(float x){ return rcpf(1.f + ex2f(-x*LOG2E)); }

// da/db/C for one direction at position bp (= b*LL + p)
__device__ __forceinline__ void stepvals(int bp, int koff, float xcv,
                                         float4 wv, float bias, float Aval,
                                         float& da, float& db, float& Cv){
    const float* pr = &g_proj[(size_t)bp*24 + koff];
    float p0 = __ldg(pr+0), p1 = __ldg(pr+1), p2 = __ldg(pr+2), p3 = __ldg(pr+3);
    float Bv = __ldg(pr+4); Cv = __ldg(pr+5);
    float xdt = fmaf(wv.x, p0, bias);
    xdt = fmaf(wv.y, p1, xdt);
    xdt = fmaf(wv.z, p2, xdt);
    xdt = fmaf(wv.w, p3, xdt);
    float tt = ex2f(fminf(xdt, 20.f) * LOG2E);
    float u  = (xdt > 20.f) ? xdt * LOG2E : lg2f(1.f + tt);
    da = ex2f(Aval * u);
    db = u * LN2 * Bv * xcv;
}

// ---------------- K0: zero d_out ----------------
__global__ void k_zero(float* out){
    int i = blockIdx.x*blockDim.x + threadIdx.x;
    if (i < BB*DD) out[i] = 0.f;
}

// ---------------- K1: in_proj GEMM (M=50176, N=256, K=128), 128x128 tile ----------------
__global__ void __launch_bounds__(256,2) k_gemm(const float* __restrict__ X, const float* __restrict__ Wm){
    __shared__ float As[32][132];
    __shared__ float Bs[32][132];
    const int row0 = blockIdx.x * 128;
    const int col0 = blockIdx.y * 128;
    const int t = threadIdx.x;
    const int tx = t & 15;
    const int ty = t >> 4;
    float c[8][8] = {};
    #pragma unroll
    for (int kb = 0; kb < 128; kb += 32){
        #pragma unroll
        for (int j = 0; j < 4; j++){
            int i = t + j*256;
            int r  = i >> 3;
            int kq = (i & 7) << 2;
            float4 v = *(const float4*)&X[(size_t)(row0+r)*128 + kb + kq];
            As[kq+0][r]=v.x; As[kq+1][r]=v.y; As[kq+2][r]=v.z; As[kq+3][r]=v.w;
        }
        #pragma unroll
        for (int j = 0; j < 4; j++){
            int i = t + j*256;
            int r  = i >> 3;
            int kq = (i & 7) << 2;
            float4 v = *(const float4*)&Wm[(size_t)(col0+r)*128 + kb + kq];
            Bs[kq+0][r]=v.x; Bs[kq+1][r]=v.y; Bs[kq+2][r]=v.z; Bs[kq+3][r]=v.w;
        }
        __syncthreads();
        #pragma unroll
        for (int kk = 0; kk < 32; kk++){
            float a[8], b[8];
            *(float4*)&a[0] = *(const float4*)&As[kk][ty*8];
            *(float4*)&a[4] = *(const float4*)&As[kk][ty*8+4];
            *(float4*)&b[0] = *(const float4*)&Bs[kk][tx*8];
            *(float4*)&b[4] = *(const float4*)&Bs[kk][tx*8+4];
            #pragma unroll
            for (int i=0;i<8;i++)
                #pragma unroll
                for (int j=0;j<8;j++)
                    c[i][j] = fmaf(a[i], b[j], c[i][j]);
        }
        __syncthreads();
    }
    #pragma unroll
    for (int i=0;i<8;i++){
        size_t ro = (size_t)(row0 + ty*8 + i)*256 + col0 + tx*8;
        *(float4*)&g_xz[ro]   = make_float4(c[i][0],c[i][1],c[i][2],c[i][3]);
        *(float4*)&g_xz[ro+4] = make_float4(c[i][4],c[i][5],c[i][6],c[i][7]);
    }
}

// ---------------- K2: depthwise conv + SiLU + fused x_dbl (warp-per-position) -------------
__global__ void __launch_bounds__(256) k_convp(const float* __restrict__ cw, const float* __restrict__ cb,
                                               const float* __restrict__ xpw){
    __shared__ float wsh[9][128];
    __shared__ float bsh[128];
    __shared__ float wp[24][132];
    const int t = threadIdx.x;   // 256
    for (int i = t; i < 1152; i += 256) wsh[i % 9][i / 9] = cw[i];
    if (t < 128) bsh[t] = cb[t];
    for (int i = t; i < 24*128; i += 256) wp[i>>7][i&127] = xpw[i];
    __syncthreads();

    const int lane = t & 31;
    const int dq = lane;                 // channel quad
    int pos = blockIdx.x*8 + (t >> 5);   // over B*L, warp = position
    int rest = pos;
    int w = rest % WW; rest /= WW;
    int h = rest % HH;
    int b = rest / HH;

    float4 s = *(const float4*)&bsh[dq*4];
    #pragma unroll
    for (int dy = -1; dy <= 1; dy++){
        int hh = h + dy;
        bool okh = (hh >= 0) && (hh < HH);
        #pragma unroll
        for (int dx = -1; dx <= 1; dx++){
            int ww = w + dx;
            if (okh && ww >= 0 && ww < WW){
                float4 xv = *(const float4*)&g_xz[((size_t)(b*LL + hh*WW + ww))*256 + dq*4];
                float4 wt = *(const float4*)&wsh[(dy+1)*3 + (dx+1)][dq*4];
                s.x = fmaf(xv.x, wt.x, s.x);
                s.y = fmaf(xv.y, wt.y, s.y);
                s.z = fmaf(xv.z, wt.z, s.z);
                s.w = fmaf(xv.w, wt.w, s.w);
            }
        }
    }
    s.x *= fsigmoid(s.x); s.y *= fsigmoid(s.y); s.z *= fsigmoid(s.z); s.w *= fsigmoid(s.w);
    *(float4*)&g_xc[(size_t)pos*128 + dq*4] = s;

    // fused x_dbl: 24 dot-products over the 128 channels this warp holds
    float pa[24];
    #pragma unroll
    for (int c = 0; c < 24; c++){
        float4 wv = *(const float4*)&wp[c][dq*4];
        pa[c] = s.x*wv.x + s.y*wv.y + s.z*wv.z + s.w*wv.w;
    }
    float outv = 0.f;
    #pragma unroll
    for (int c = 0; c < 24; c++){
        float v = pa[c];
        #pragma unroll
        for (int o = 16; o > 0; o >>= 1) v += __shfl_xor_sync(~0u, v, o);
        if (lane == c) outv = v;
    }
    if (lane < 24) g_proj[(size_t)pos*24 + lane] = outv;
}

// ---------------- K3: scan pass 1 — paired directions, segment summaries ----------------
// blockIdx: x=segment s (row for pair0 / column for pair1), y=b, z=pair
__global__ void k_pass1(const float* __restrict__ dtw, const float* __restrict__ dtb,
                        const float* __restrict__ alog){
    const int s = blockIdx.x, b = blockIdx.y, pair = blockIdx.z;
    const int d = threadIdx.x;
    const int kf = pair*2, kb_ = pair*2 + 1;
    float4 wf = *(const float4*)&dtw[(size_t)(kf*128 + d)*4];
    float4 wb = *(const float4*)&dtw[(size_t)(kb_*128 + d)*4];
    float bf = dtb[kf*128 + d], bbs = dtb[kb_*128 + d];
    float Af = -ex2f(alog[kf*128 + d] * LOG2E);
    float Ab = -ex2f(alog[kb_*128 + d] * LOG2E);

    float hf = 0.f, Pf = 1.f;       // forward state & prod
    float hb = 0.f, Pb = 1.f;       // backward summary (computed in fwd order)
    #pragma unroll 2
    for (int i = 0; i < SEGLEN; i++){
        int p  = (pair == 0) ? (s*WW + i) : (i*WW + s);
        int bp = b*LL + p;
        float xcv = g_xc[(size_t)bp*128 + d];
        float da, db, Cv;
        stepvals(bp, kf*6, xcv, wf, bf, Af, da, db, Cv);
        hf = fmaf(da, hf, db);
        Pf *= da;
        stepvals(bp, kb_*6, xcv, wb, bbs, Ab, da, db, Cv);
        hb = fmaf(db, Pb, hb);
        Pb *= da;
    }
    const int gf = b*4 + kf, gb = b*4 + kb_;
    size_t if_ = ((size_t)gf*NSEG + s)*128 + d;
    size_t ib_ = ((size_t)gb*NSEG + (NSEG-1-s))*128 + d;
    g_hend[if_]  = hf;  g_aprod[if_] = Pf;
    g_hend[ib_]  = hb;  g_aprod[ib_] = Pb;
}

// ---------------- K4: combine (prefix over segments, per scan-chain) ----------------
__global__ void k_comb(){
    const int g = blockIdx.x, d = threadIdx.x;
    float carry = 0.f;
    #pragma unroll 4
    for (int s = 0; s < NSEG; s++){
        size_t idx = ((size_t)g*NSEG + s)*128 + d;
        g_init[idx] = carry;
        carry = fmaf(g_aprod[idx], carry, g_hend[idx]);
    }
}

// ---------------- K5/K6: scan pass 2 — paired directions, fused y output ----------------
template<int PAIR>
__global__ void __launch_bounds__(128) k_pass2(const float* __restrict__ dtw, const float* __restrict__ dtb,
                                               const float* __restrict__ alog, const float* __restrict__ Ds){
    __shared__ float ybuf[SEGLEN][128];
    const int s = blockIdx.x, b = blockIdx.y;
    const int d = threadIdx.x;
    const int kf = PAIR*2, kb_ = PAIR*2 + 1;
    float4 wf = *(const float4*)&dtw[(size_t)(kf*128 + d)*4];
    float4 wb = *(const float4*)&dtw[(size_t)(kb_*128 + d)*4];
    float bf = dtb[kf*128 + d], bbs = dtb[kb_*128 + d];
    float Af = -ex2f(alog[kf*128 + d] * LOG2E);
    float Ab = -ex2f(alog[kb_*128 + d] * LOG2E);
    const int gf = b*4 + kf, gb = b*4 + kb_;

    // backward direction: descending traversal of this segment
    float hb = g_init[((size_t)gb*NSEG + (NSEG-1-s))*128 + d];
    #pragma unroll 2
    for (int i = SEGLEN-1; i >= 0; i--){
        int p  = (PAIR == 0) ? (s*WW + i) : (i*WW + s);
        int bp = b*LL + p;
        float xcv = g_xc[(size_t)bp*128 + d];
        float da, db, Cv;
        stepvals(bp, kb_*6, xcv, wb, bbs, Ab, da, db, Cv);
        hb = fmaf(da, hb, db);
        ybuf[i][d] = hb * Cv;
    }
    // forward direction + merge
    float sumDs = 0.f;
    if (PAIR == 0) sumDs = Ds[d] + Ds[128+d] + Ds[256+d] + Ds[384+d];
    float hf = g_init[((size_t)gf*NSEG + s)*128 + d];
    #pragma unroll 2
    for (int i = 0; i < SEGLEN; i++){
        int p  = (PAIR == 0) ? (s*WW + i) : (i*WW + s);
        int bp = b*LL + p;
        float xcv = g_xc[(size_t)bp*128 + d];
        float da, db, Cv;
        stepvals(bp, kf*6, xcv, wf, bf, Af, da, db, Cv);
        hf = fmaf(da, hf, db);
        float val = fmaf(hf, Cv, ybuf[i][d]);
        if (PAIR == 0){
            g_ysum[(size_t)bp*128 + d] = fmaf(xcv, sumDs, val);
        } else {
            atomicAdd(&g_ysum[(size_t)bp*128 + d], val);
        }
    }
}

// ---------------- K7: LayerNorm + SiLU gate + spatial mean ----------------
__global__ void __launch_bounds__(256) k_final(const float* __restrict__ nw, const float* __restrict__ nb,
                                               float* __restrict__ out){
    const int b = blockIdx.y;
    const int t = threadIdx.x;        // 256
    const int warp = t >> 5, lane = t & 31;
    const int d4 = lane*4;
    float4 w4 = *(const float4*)&nw[d4];
    float4 b4 = *(const float4*)&nb[d4];

    float4 acc = make_float4(0.f,0.f,0.f,0.f);
    #pragma unroll 2
    for (int j = 0; j < 8; j++){
        int p = blockIdx.x*64 + warp*8 + j;
        size_t base = ((size_t)(b*LL + p))*128 + d4;
        float4 v = *(const float4*)&g_ysum[base];
        float sm = v.x+v.y+v.z+v.w;
        #pragma unroll
        for (int o = 16; o > 0; o >>= 1) sm += __shfl_xor_sync(~0u, sm, o);
        float mu = sm * (1.f/128.f);
        float4 dv = make_float4(v.x-mu, v.y-mu, v.z-mu, v.w-mu);
        float s2 = dv.x*dv.x + dv.y*dv.y + dv.z*dv.z + dv.w*dv.w;
        #pragma unroll
        for (int o = 16; o > 0; o >>= 1) s2 += __shfl_xor_sync(~0u, s2, o);
        float rstd = rsqrtf(s2 * (1.f/128.f) + 1e-5f);
        float4 z = *(const float4*)&g_xz[((size_t)(b*LL + p))*256 + 128 + d4];
        float gx = z.x*fsigmoid(z.x), gy = z.y*fsigmoid(z.y);
        float gz = z.z*fsigmoid(z.z), gw = z.w*fsigmoid(z.w);
        acc.x = fmaf(fmaf(dv.x*rstd, w4.x, b4.x), gx, acc.x);
        acc.y = fmaf(fmaf(dv.y*rstd, w4.y, b4.y), gy, acc.y);
        acc.z = fmaf(fmaf(dv.z*rstd, w4.z, b4.z), gz, acc.z);
        acc.w = fmaf(fmaf(dv.w*rstd, w4.w, b4.w), gw, acc.w);
    }
    const float sc = 1.f/(float)LL;
    atomicAdd(&out[b*128 + d4 + 0], acc.x*sc);
    atomicAdd(&out[b*128 + d4 + 1], acc.y*sc);
    atomicAdd(&out[b*128 + d4 + 2], acc.z*sc);
    atomicAdd(&out[b*128 + d4 + 3], acc.w*sc);
}

// ---------------- launch ----------------
extern "C" void kernel_launch(void* const* d_in, const int* in_sizes, int n_in,
                              void* d_out, int out_size){
    const float* x    = (const float*)d_in[0];
    const float* inw  = (const float*)d_in[1];
    const float* cw   = (const float*)d_in[2];
    const float* cb   = (const float*)d_in[3];
    const float* xpw  = (const float*)d_in[4];
    const float* dtw  = (const float*)d_in[5];
    const float* dtb  = (const float*)d_in[6];
    const float* alog = (const float*)d_in[7];
    const float* Ds   = (const float*)d_in[8];
    const float* onw  = (const float*)d_in[9];
    const float* onb  = (const float*)d_in[10];
    float* out = (float*)d_out;

    k_zero<<<(BB*DD + 255)/256, 256>>>(out);
    k_gemm<<<dim3((BB*LL)/128, 2), 256>>>(x, inw);
    k_convp<<<(BB*LL)/8, 256>>>(cw, cb, xpw);
    k_pass1<<<dim3(NSEG, BB, 2), 128>>>(dtw, dtb, alog);
    k_comb<<<64, 128>>>();
    k_pass2<0><<<dim3(NSEG, BB), 128>>>(dtw, dtb, alog, Ds);
    k_pass2<1><<<dim3(NSEG, BB), 128>>>(dtw, dtb, alog, Ds);
    k_final<<<dim3(LL/64, BB), 256>>>(onw, onb, out);
}

// round 4
// speedup vs baseline: 7.2706x; 1.1570x over previous
#include <cuda_runtime.h>
#include <cuda_bf16.h>
#include <cstdint>

// ---------------- problem constants ----------------
#define BB 16
#define HH 56
#define WW 56
#define LL (HH*WW)      // 3136
#define DD 128
#define KK 4
#define NSEG 56
#define SEGLEN 56       // 56*56 = 3136

#define LOG2E 1.4426950408889634f
#define LN2   0.6931471805599453f

// ---------------- scratch (device globals; no allocs allowed) ----------------
__device__ float g_xz   [(size_t)BB*LL*256];     // in_proj output (xi | z), channel-last
__device__ float g_xc   [(size_t)BB*LL*DD];      // conv+silu output, channel-last
__device__ float g_proj [(size_t)BB*LL*24];      // x_dbl: per pos, [k*6 + c]
__device__ float g_ysum [(size_t)BB*LL*DD];      // pair01 y + Ds*xc
__device__ float g_ysum2[(size_t)BB*LL*DD];      // pair23 y
__device__ float g_hend [(size_t)64*NSEG*DD];
__device__ float g_aprod[(size_t)64*NSEG*DD];
__device__ float g_init [(size_t)64*NSEG*DD];

// ---------------- math helpers (MUFU) ----------------
__device__ __forceinline__ float ex2f(float x){ float y; asm("ex2.approx.ftz.f32 %0,%1;" : "=f"(y) : "f"(x)); return y; }
__device__ __forceinline__ float lg2f(float x){ float y; asm("lg2.approx.ftz.f32 %0,%1;" : "=f"(y) : "f"(x)); return y; }
__device__ __forceinline__ float rcpf(float x){ float y; asm("rcp.approx.ftz.f32 %0,%1;" : "=f"(y) : "f"(x)); return y; }
__device__ __forceinline__ float fsigmoid(float x){ return rcpf(1.f + ex2f(-x*LOG2E)); }

// da/db/C for one direction at position bp (= b*LL + p)
__device__ __forceinline__ void stepvals(int bp, int koff, float xcv,
                                         float4 wv, float bias, float Aval,
                                         float& da, float& db, float& Cv){
    const float* pr = &g_proj[(size_t)bp*24 + koff];
    float p0 = __ldg(pr+0), p1 = __ldg(pr+1), p2 = __ldg(pr+2), p3 = __ldg(pr+3);
    float Bv = __ldg(pr+4); Cv = __ldg(pr+5);
    float xdt = fmaf(wv.x, p0, bias);
    xdt = fmaf(wv.y, p1, xdt);
    xdt = fmaf(wv.z, p2, xdt);
    xdt = fmaf(wv.w, p3, xdt);
    float tt = ex2f(fminf(xdt, 20.f) * LOG2E);
    float u  = (xdt > 20.f) ? xdt * LOG2E : lg2f(1.f + tt);
    da = ex2f(Aval * u);
    db = u * LN2 * Bv * xcv;
}

// ---------------- K0: zero d_out ----------------
__global__ void k_zero(float* out){
    int i = blockIdx.x*blockDim.x + threadIdx.x;
    if (i < BB*DD) out[i] = 0.f;
}

// ---------------- tensor-core GEMM helpers ----------------
__device__ __forceinline__ void ldsm4(uint32_t* r, uint32_t addr){
    asm volatile("ldmatrix.sync.aligned.m8n8.x4.shared.b16 {%0,%1,%2,%3}, [%4];"
        : "=r"(r[0]),"=r"(r[1]),"=r"(r[2]),"=r"(r[3]) : "r"(addr));
}
__device__ __forceinline__ void mma16816(float* c, const uint32_t* a, const uint32_t* b){
    asm volatile("mma.sync.aligned.m16n8k16.row.col.f32.bf16.bf16.f32 "
        "{%0,%1,%2,%3}, {%4,%5,%6,%7}, {%8,%9}, {%0,%1,%2,%3};"
        : "+f"(c[0]),"+f"(c[1]),"+f"(c[2]),"+f"(c[3])
        : "r"(a[0]),"r"(a[1]),"r"(a[2]),"r"(a[3]), "r"(b[0]),"r"(b[1]));
}
__device__ __forceinline__ uint32_t pkbf(__nv_bfloat162 h){ return *reinterpret_cast<uint32_t*>(&h); }

// ---------------- K1: in_proj GEMM (M=50176,N=256,K=128) bf16 split-precision MMA -------
// block tile 128x64, 8 warps (4m x 2n), warp tile 32x32
__global__ void __launch_bounds__(256) k_gemm(const float* __restrict__ X, const float* __restrict__ Wm){
    __shared__ __align__(16) __nv_bfloat16 sA[2][128][40];   // [hi/lo][m][k(32)+8pad]
    __shared__ uint32_t sB[2][64][18];                       // packed bf16x2 k-pairs
    const int t = threadIdx.x;
    const int row0 = blockIdx.x * 128;
    const int col0 = blockIdx.y * 64;
    const int wid = t >> 5, lane = t & 31;
    const int mw = wid & 3, nw = wid >> 2;
    float acc[2][4][4] = {};

    for (int kb = 0; kb < 128; kb += 32){
        // load A tile 128x32 (4 float4 per thread), split hi/lo
        #pragma unroll
        for (int j = 0; j < 4; j++){
            int fid = t + j*256;
            int r = fid >> 3, kq = (fid & 7) << 2;
            float4 v = *(const float4*)&X[(size_t)(row0+r)*128 + kb + kq];
            __nv_bfloat162 h01 = __floats2bfloat162_rn(v.x, v.y);
            __nv_bfloat162 h23 = __floats2bfloat162_rn(v.z, v.w);
            float2 f01 = __bfloat1622float2(h01);
            float2 f23 = __bfloat1622float2(h23);
            __nv_bfloat162 l01 = __floats2bfloat162_rn(v.x - f01.x, v.y - f01.y);
            __nv_bfloat162 l23 = __floats2bfloat162_rn(v.z - f23.x, v.w - f23.y);
            *(__nv_bfloat162*)&sA[0][r][kq]   = h01;
            *(__nv_bfloat162*)&sA[0][r][kq+2] = h23;
            *(__nv_bfloat162*)&sA[1][r][kq]   = l01;
            *(__nv_bfloat162*)&sA[1][r][kq+2] = l23;
        }
        // load B tile 64x32 (2 float4 per thread)
        #pragma unroll
        for (int j = 0; j < 2; j++){
            int fid = t + j*256;
            int r = fid >> 3, kq = (fid & 7) << 2;
            float4 v = *(const float4*)&Wm[(size_t)(col0+r)*128 + kb + kq];
            __nv_bfloat162 h01 = __floats2bfloat162_rn(v.x, v.y);
            __nv_bfloat162 h23 = __floats2bfloat162_rn(v.z, v.w);
            float2 f01 = __bfloat1622float2(h01);
            float2 f23 = __bfloat1622float2(h23);
            sB[0][r][(kq>>1)  ] = pkbf(h01);
            sB[0][r][(kq>>1)+1] = pkbf(h23);
            sB[1][r][(kq>>1)  ] = pkbf(__floats2bfloat162_rn(v.x - f01.x, v.y - f01.y));
            sB[1][r][(kq>>1)+1] = pkbf(__floats2bfloat162_rn(v.z - f23.x, v.w - f23.y));
        }
        __syncthreads();
        #pragma unroll
        for (int ks = 0; ks < 2; ks++){
            uint32_t ah[2][4], al[2][4];
            #pragma unroll
            for (int f = 0; f < 2; f++){
                int rr = mw*32 + f*16 + (lane & 15);
                int cc = ks*16 + (lane >> 4)*8;
                ldsm4(ah[f], (uint32_t)__cvta_generic_to_shared(&sA[0][rr][cc]));
                ldsm4(al[f], (uint32_t)__cvta_generic_to_shared(&sA[1][rr][cc]));
            }
            #pragma unroll
            for (int j = 0; j < 4; j++){
                int nr = nw*32 + j*8 + (lane >> 2);
                int kp = ks*8 + (lane & 3);
                uint32_t bh[2] = { sB[0][nr][kp], sB[0][nr][kp+4] };
                uint32_t bl[2] = { sB[1][nr][kp], sB[1][nr][kp+4] };
                #pragma unroll
                for (int f = 0; f < 2; f++){
                    mma16816(acc[f][j], ah[f], bh);
                    mma16816(acc[f][j], ah[f], bl);
                    mma16816(acc[f][j], al[f], bh);
                }
            }
        }
        __syncthreads();
    }
    // epilogue
    #pragma unroll
    for (int f = 0; f < 2; f++){
        #pragma unroll
        for (int j = 0; j < 4; j++){
            int r = row0 + mw*32 + f*16 + (lane >> 2);
            int c = col0 + nw*32 + j*8 + (lane & 3)*2;
            *(float2*)&g_xz[(size_t)r*256 + c]     = make_float2(acc[f][j][0], acc[f][j][1]);
            *(float2*)&g_xz[(size_t)(r+8)*256 + c] = make_float2(acc[f][j][2], acc[f][j][3]);
        }
    }
}

// ---------------- K2: depthwise conv + SiLU + fused x_dbl (warp-per-position) -------------
__global__ void __launch_bounds__(256) k_convp(const float* __restrict__ cw, const float* __restrict__ cb,
                                               const float* __restrict__ xpw){
    __shared__ float wsh[9][128];
    __shared__ float bsh[128];
    __shared__ float wp[24][132];
    __shared__ float red[8][32][25];
    const int t = threadIdx.x;   // 256
    for (int i = t; i < 1152; i += 256) wsh[i % 9][i / 9] = cw[i];
    if (t < 128) bsh[t] = cb[t];
    for (int i = t; i < 24*128; i += 256) wp[i>>7][i&127] = xpw[i];
    __syncthreads();

    const int lane = t & 31;
    const int warpid = t >> 5;
    const int dq = lane;
    int pos = blockIdx.x*8 + warpid;
    int rest = pos;
    int w = rest % WW; rest /= WW;
    int h = rest % HH;
    int b = rest / HH;

    float4 s = *(const float4*)&bsh[dq*4];
    #pragma unroll
    for (int dy = -1; dy <= 1; dy++){
        int hh = h + dy;
        bool okh = (hh >= 0) && (hh < HH);
        #pragma unroll
        for (int dx = -1; dx <= 1; dx++){
            int ww = w + dx;
            if (okh && ww >= 0 && ww < WW){
                float4 xv = *(const float4*)&g_xz[((size_t)(b*LL + hh*WW + ww))*256 + dq*4];
                float4 wt = *(const float4*)&wsh[(dy+1)*3 + (dx+1)][dq*4];
                s.x = fmaf(xv.x, wt.x, s.x);
                s.y = fmaf(xv.y, wt.y, s.y);
                s.z = fmaf(xv.z, wt.z, s.z);
                s.w = fmaf(xv.w, wt.w, s.w);
            }
        }
    }
    s.x *= fsigmoid(s.x); s.y *= fsigmoid(s.y); s.z *= fsigmoid(s.z); s.w *= fsigmoid(s.w);
    *(float4*)&g_xc[(size_t)pos*128 + dq*4] = s;

    // fused x_dbl: per-lane partials, smem transpose reduce
    #pragma unroll
    for (int c = 0; c < 24; c++){
        float4 wv = *(const float4*)&wp[c][dq*4];
        red[warpid][lane][c] = s.x*wv.x + s.y*wv.y + s.z*wv.z + s.w*wv.w;
    }
    __syncwarp();
    if (lane < 24){
        float outv = 0.f;
        #pragma unroll 8
        for (int i = 0; i < 32; i++) outv += red[warpid][i][lane];
        g_proj[(size_t)pos*24 + lane] = outv;
    }
}

// ---------------- K3: scan pass 1 — paired directions, segment summaries ----------------
__global__ void k_pass1(const float* __restrict__ dtw, const float* __restrict__ dtb,
                        const float* __restrict__ alog){
    const int s = blockIdx.x, b = blockIdx.y, pair = blockIdx.z;
    const int d = threadIdx.x;
    const int kf = pair*2, kb_ = pair*2 + 1;
    float4 wf = *(const float4*)&dtw[(size_t)(kf*128 + d)*4];
    float4 wb = *(const float4*)&dtw[(size_t)(kb_*128 + d)*4];
    float bf = dtb[kf*128 + d], bbs = dtb[kb_*128 + d];
    float Af = -ex2f(alog[kf*128 + d] * LOG2E);
    float Ab = -ex2f(alog[kb_*128 + d] * LOG2E);

    float hf = 0.f, Pf = 1.f;
    float hb = 0.f, Pb = 1.f;
    #pragma unroll 2
    for (int i = 0; i < SEGLEN; i++){
        int p  = (pair == 0) ? (s*WW + i) : (i*WW + s);
        int bp = b*LL + p;
        float xcv = g_xc[(size_t)bp*128 + d];
        float da, db, Cv;
        stepvals(bp, kf*6, xcv, wf, bf, Af, da, db, Cv);
        hf = fmaf(da, hf, db);
        Pf *= da;
        stepvals(bp, kb_*6, xcv, wb, bbs, Ab, da, db, Cv);
        hb = fmaf(db, Pb, hb);
        Pb *= da;
    }
    const int gf = b*4 + kf, gb = b*4 + kb_;
    size_t if_ = ((size_t)gf*NSEG + s)*128 + d;
    size_t ib_ = ((size_t)gb*NSEG + (NSEG-1-s))*128 + d;
    g_hend[if_]  = hf;  g_aprod[if_] = Pf;
    g_hend[ib_]  = hb;  g_aprod[ib_] = Pb;
}

// ---------------- K4: combine (prefix over segments, per scan-chain) ----------------
__global__ void k_comb(){
    const int g = blockIdx.x, d = threadIdx.x;
    float carry = 0.f;
    #pragma unroll 4
    for (int s = 0; s < NSEG; s++){
        size_t idx = ((size_t)g*NSEG + s)*128 + d;
        g_init[idx] = carry;
        carry = fmaf(g_aprod[idx], carry, g_hend[idx]);
    }
}

// ---------------- K5: scan pass 2 — both pairs concurrent (z), no atomics ----------------
__global__ void __launch_bounds__(128) k_pass2(const float* __restrict__ dtw, const float* __restrict__ dtb,
                                               const float* __restrict__ alog, const float* __restrict__ Ds){
    __shared__ float ybuf[SEGLEN][128];
    const int s = blockIdx.x, b = blockIdx.y, pair = blockIdx.z;
    const int d = threadIdx.x;
    const int kf = pair*2, kb_ = pair*2 + 1;
    float4 wf = *(const float4*)&dtw[(size_t)(kf*128 + d)*4];
    float4 wb = *(const float4*)&dtw[(size_t)(kb_*128 + d)*4];
    float bf = dtb[kf*128 + d], bbs = dtb[kb_*128 + d];
    float Af = -ex2f(alog[kf*128 + d] * LOG2E);
    float Ab = -ex2f(alog[kb_*128 + d] * LOG2E);
    const int gf = b*4 + kf, gb = b*4 + kb_;

    // backward direction: descending traversal of this segment
    float hb = g_init[((size_t)gb*NSEG + (NSEG-1-s))*128 + d];
    #pragma unroll 2
    for (int i = SEGLEN-1; i >= 0; i--){
        int p  = (pair == 0) ? (s*WW + i) : (i*WW + s);
        int bp = b*LL + p;
        float xcv = g_xc[(size_t)bp*128 + d];
        float da, db, Cv;
        stepvals(bp, kb_*6, xcv, wb, bbs, Ab, da, db, Cv);
        hb = fmaf(da, hb, db);
        ybuf[i][d] = hb * Cv;
    }
    // forward direction + merge
    float sumDs = Ds[d] + Ds[128+d] + Ds[256+d] + Ds[384+d];
    float hf = g_init[((size_t)gf*NSEG + s)*128 + d];
    #pragma unroll 2
    for (int i = 0; i < SEGLEN; i++){
        int p  = (pair == 0) ? (s*WW + i) : (i*WW + s);
        int bp = b*LL + p;
        float xcv = g_xc[(size_t)bp*128 + d];
        float da, db, Cv;
        stepvals(bp, kf*6, xcv, wf, bf, Af, da, db, Cv);
        hf = fmaf(da, hf, db);
        float val = fmaf(hf, Cv, ybuf[i][d]);
        if (pair == 0){
            g_ysum[(size_t)bp*128 + d] = fmaf(xcv, sumDs, val);
        } else {
            g_ysum2[(size_t)bp*128 + d] = val;
        }
    }
}

// ---------------- K6: LayerNorm + SiLU gate + spatial mean ----------------
__global__ void __launch_bounds__(256) k_final(const float* __restrict__ nw, const float* __restrict__ nb,
                                               float* __restrict__ out){
    const int b = blockIdx.y;
    const int t = threadIdx.x;
    const int warp = t >> 5, lane = t & 31;
    const int d4 = lane*4;
    float4 w4 = *(const float4*)&nw[d4];
    float4 b4 = *(const float4*)&nb[d4];

    float4 acc = make_float4(0.f,0.f,0.f,0.f);
    #pragma unroll 2
    for (int j = 0; j < 8; j++){
        int p = blockIdx.x*64 + warp*8 + j;
        size_t base = ((size_t)(b*LL + p))*128 + d4;
        float4 v  = *(const float4*)&g_ysum[base];
        float4 v2 = *(const float4*)&g_ysum2[base];
        v.x += v2.x; v.y += v2.y; v.z += v2.z; v.w += v2.w;
        float sm = v.x+v.y+v.z+v.w;
        #pragma unroll
        for (int o = 16; o > 0; o >>= 1) sm += __shfl_xor_sync(~0u, sm, o);
        float mu = sm * (1.f/128.f);
        float4 dv = make_float4(v.x-mu, v.y-mu, v.z-mu, v.w-mu);
        float s2 = dv.x*dv.x + dv.y*dv.y + dv.z*dv.z + dv.w*dv.w;
        #pragma unroll
        for (int o = 16; o > 0; o >>= 1) s2 += __shfl_xor_sync(~0u, s2, o);
        float rstd = rsqrtf(s2 * (1.f/128.f) + 1e-5f);
        float4 z = *(const float4*)&g_xz[((size_t)(b*LL + p))*256 + 128 + d4];
        float gx = z.x*fsigmoid(z.x), gy = z.y*fsigmoid(z.y);
        float gz = z.z*fsigmoid(z.z), gw = z.w*fsigmoid(z.w);
        acc.x = fmaf(fmaf(dv.x*rstd, w4.x, b4.x), gx, acc.x);
        acc.y = fmaf(fmaf(dv.y*rstd, w4.y, b4.y), gy, acc.y);
        acc.z = fmaf(fmaf(dv.z*rstd, w4.z, b4.z), gz, acc.z);
        acc.w = fmaf(fmaf(dv.w*rstd, w4.w, b4.w), gw, acc.w);
    }
    const float sc = 1.f/(float)LL;
    atomicAdd(&out[b*128 + d4 + 0], acc.x*sc);
    atomicAdd(&out[b*128 + d4 + 1], acc.y*sc);
    atomicAdd(&out[b*128 + d4 + 2], acc.z*sc);
    atomicAdd(&out[b*128 + d4 + 3], acc.w*sc);
}

// ---------------- launch ----------------
extern "C" void kernel_launch(void* const* d_in, const int* in_sizes, int n_in,
                              void* d_out, int out_size){
    const float* x    = (const float*)d_in[0];
    const float* inw  = (const float*)d_in[1];
    const float* cw   = (const float*)d_in[2];
    const float* cb   = (const float*)d_in[3];
    const float* xpw  = (const float*)d_in[4];
    const float* dtw  = (const float*)d_in[5];
    const float* dtb  = (const float*)d_in[6];
    const float* alog = (const float*)d_in[7];
    const float* Ds   = (const float*)d_in[8];
    const float* onw  = (const float*)d_in[9];
    const float* onb  = (const float*)d_in[10];
    float* out = (float*)d_out;

    k_zero<<<(BB*DD + 255)/256, 256>>>(out);
    k_gemm<<<dim3((BB*LL)/128, 4), 256>>>(x, inw);
    k_convp<<<(BB*LL)/8, 256>>>(cw, cb, xpw);
    k_pass1<<<dim3(NSEG, BB, 2), 128>>>(dtw, dtb, alog);
    k_comb<<<64, 128>>>();
    k_pass2<<<dim3(NSEG, BB, 2), 128>>>(dtw, dtb, alog, Ds);
    k_final<<<dim3(LL/64, BB), 256>>>(onw, onb, out);
}

// round 5
// speedup vs baseline: 7.4337x; 1.0224x over previous
#include <cuda_runtime.h>
#include <cuda_bf16.h>
#include <cstdint>

// ---------------- problem constants ----------------
#define BB 16
#define HH 56
#define WW 56
#define LL (HH*WW)      // 3136
#define DD 128
#define KK 4
#define NSEG 56
#define SEGLEN 56       // 56*56 = 3136

#define LOG2E 1.4426950408889634f
#define LN2   0.6931471805599453f

// ---------------- scratch (device globals; no allocs allowed) ----------------
__device__ float g_xz   [(size_t)BB*LL*256];     // in_proj output (xi | z), channel-last
__device__ float g_xc   [(size_t)BB*LL*DD];      // conv+silu output, channel-last
__device__ float g_proj [(size_t)BB*LL*24];      // x_dbl: per pos, [k*6 + c]
__device__ float g_ysum [(size_t)BB*LL*DD];      // pair01 y + Ds*xc
__device__ float g_ysum2[(size_t)BB*LL*DD];      // pair23 y
__device__ float g_hend [(size_t)64*NSEG*DD];
__device__ float g_aprod[(size_t)64*NSEG*DD];
__device__ float g_init [(size_t)64*NSEG*DD];
__device__ unsigned int g_cnt[32];               // per (b,pair) completion counters

// ---------------- math helpers (MUFU) ----------------
__device__ __forceinline__ float ex2f(float x){ float y; asm("ex2.approx.ftz.f32 %0,%1;" : "=f"(y) : "f"(x)); return y; }
__device__ __forceinline__ float lg2f(float x){ float y; asm("lg2.approx.ftz.f32 %0,%1;" : "=f"(y) : "f"(x)); return y; }
__device__ __forceinline__ float rcpf(float x){ float y; asm("rcp.approx.ftz.f32 %0,%1;" : "=f"(y) : "f"(x)); return y; }
__device__ __forceinline__ float fsigmoid(float x){ return rcpf(1.f + ex2f(-x*LOG2E)); }

// softplus in log2 domain: returns u = softplus(x)*log2e
__device__ __forceinline__ float sp_u(float x){
    float tt = ex2f(fminf(x, 20.f) * LOG2E);
    return (x > 20.f) ? x * LOG2E : lg2f(1.f + tt);
}

// ---------------- K0: zero d_out + counters ----------------
__global__ void k_zero(float* out){
    int i = blockIdx.x*blockDim.x + threadIdx.x;
    if (i < BB*DD) out[i] = 0.f;
    if (i < 32) g_cnt[i] = 0u;
}

// ---------------- tensor-core GEMM helpers ----------------
__device__ __forceinline__ void ldsm4(uint32_t* r, uint32_t addr){
    asm volatile("ldmatrix.sync.aligned.m8n8.x4.shared.b16 {%0,%1,%2,%3}, [%4];"
        : "=r"(r[0]),"=r"(r[1]),"=r"(r[2]),"=r"(r[3]) : "r"(addr));
}
__device__ __forceinline__ void mma16816(float* c, const uint32_t* a, const uint32_t* b){
    asm volatile("mma.sync.aligned.m16n8k16.row.col.f32.bf16.bf16.f32 "
        "{%0,%1,%2,%3}, {%4,%5,%6,%7}, {%8,%9}, {%0,%1,%2,%3};"
        : "+f"(c[0]),"+f"(c[1]),"+f"(c[2]),"+f"(c[3])
        : "r"(a[0]),"r"(a[1]),"r"(a[2]),"r"(a[3]), "r"(b[0]),"r"(b[1]));
}
__device__ __forceinline__ uint32_t pkbf(__nv_bfloat162 h){ return *reinterpret_cast<uint32_t*>(&h); }

// ---------------- K1: in_proj GEMM (M=50176,N=256,K=128) bf16 split-precision MMA -------
__global__ void __launch_bounds__(256) k_gemm(const float* __restrict__ X, const float* __restrict__ Wm){
    __shared__ __align__(16) __nv_bfloat16 sA[2][128][40];
    __shared__ uint32_t sB[2][64][18];
    const int t = threadIdx.x;
    const int row0 = blockIdx.x * 128;
    const int col0 = blockIdx.y * 64;
    const int wid = t >> 5, lane = t & 31;
    const int mw = wid & 3, nw = wid >> 2;
    float acc[2][4][4] = {};

    for (int kb = 0; kb < 128; kb += 32){
        #pragma unroll
        for (int j = 0; j < 4; j++){
            int fid = t + j*256;
            int r = fid >> 3, kq = (fid & 7) << 2;
            float4 v = *(const float4*)&X[(size_t)(row0+r)*128 + kb + kq];
            __nv_bfloat162 h01 = __floats2bfloat162_rn(v.x, v.y);
            __nv_bfloat162 h23 = __floats2bfloat162_rn(v.z, v.w);
            float2 f01 = __bfloat1622float2(h01);
            float2 f23 = __bfloat1622float2(h23);
            *(__nv_bfloat162*)&sA[0][r][kq]   = h01;
            *(__nv_bfloat162*)&sA[0][r][kq+2] = h23;
            *(__nv_bfloat162*)&sA[1][r][kq]   = __floats2bfloat162_rn(v.x - f01.x, v.y - f01.y);
            *(__nv_bfloat162*)&sA[1][r][kq+2] = __floats2bfloat162_rn(v.z - f23.x, v.w - f23.y);
        }
        #pragma unroll
        for (int j = 0; j < 2; j++){
            int fid = t + j*256;
            int r = fid >> 3, kq = (fid & 7) << 2;
            float4 v = *(const float4*)&Wm[(size_t)(col0+r)*128 + kb + kq];
            __nv_bfloat162 h01 = __floats2bfloat162_rn(v.x, v.y);
            __nv_bfloat162 h23 = __floats2bfloat162_rn(v.z, v.w);
            float2 f01 = __bfloat1622float2(h01);
            float2 f23 = __bfloat1622float2(h23);
            sB[0][r][(kq>>1)  ] = pkbf(h01);
            sB[0][r][(kq>>1)+1] = pkbf(h23);
            sB[1][r][(kq>>1)  ] = pkbf(__floats2bfloat162_rn(v.x - f01.x, v.y - f01.y));
            sB[1][r][(kq>>1)+1] = pkbf(__floats2bfloat162_rn(v.z - f23.x, v.w - f23.y));
        }
        __syncthreads();
        #pragma unroll
        for (int ks = 0; ks < 2; ks++){
            uint32_t ah[2][4], al[2][4];
            #pragma unroll
            for (int f = 0; f < 2; f++){
                int rr = mw*32 + f*16 + (lane & 15);
                int cc = ks*16 + (lane >> 4)*8;
                ldsm4(ah[f], (uint32_t)__cvta_generic_to_shared(&sA[0][rr][cc]));
                ldsm4(al[f], (uint32_t)__cvta_generic_to_shared(&sA[1][rr][cc]));
            }
            #pragma unroll
            for (int j = 0; j < 4; j++){
                int nr = nw*32 + j*8 + (lane >> 2);
                int kp = ks*8 + (lane & 3);
                uint32_t bh[2] = { sB[0][nr][kp], sB[0][nr][kp+4] };
                uint32_t bl[2] = { sB[1][nr][kp], sB[1][nr][kp+4] };
                #pragma unroll
                for (int f = 0; f < 2; f++){
                    mma16816(acc[f][j], ah[f], bh);
                    mma16816(acc[f][j], ah[f], bl);
                    mma16816(acc[f][j], al[f], bh);
                }
            }
        }
        __syncthreads();
    }
    #pragma unroll
    for (int f = 0; f < 2; f++){
        #pragma unroll
        for (int j = 0; j < 4; j++){
            int r = row0 + mw*32 + f*16 + (lane >> 2);
            int c = col0 + nw*32 + j*8 + (lane & 3)*2;
            *(float2*)&g_xz[(size_t)r*256 + c]     = make_float2(acc[f][j][0], acc[f][j][1]);
            *(float2*)&g_xz[(size_t)(r+8)*256 + c] = make_float2(acc[f][j][2], acc[f][j][3]);
        }
    }
}

// ---------------- K2: depthwise conv + SiLU + fused x_dbl (warp-per-position) -------------
__global__ void __launch_bounds__(256) k_convp(const float* __restrict__ cw, const float* __restrict__ cb,
                                               const float* __restrict__ xpw){
    __shared__ float wsh[9][128];
    __shared__ float bsh[128];
    __shared__ float wp[24][132];
    __shared__ float red[8][32][25];
    const int t = threadIdx.x;
    for (int i = t; i < 1152; i += 256) wsh[i % 9][i / 9] = cw[i];
    if (t < 128) bsh[t] = cb[t];
    for (int i = t; i < 24*128; i += 256) wp[i>>7][i&127] = xpw[i];
    __syncthreads();

    const int lane = t & 31;
    const int warpid = t >> 5;
    const int dq = lane;
    int pos = blockIdx.x*8 + warpid;
    int rest = pos;
    int w = rest % WW; rest /= WW;
    int h = rest % HH;
    int b = rest / HH;

    float4 s = *(const float4*)&bsh[dq*4];
    #pragma unroll
    for (int dy = -1; dy <= 1; dy++){
        int hh = h + dy;
        bool okh = (hh >= 0) && (hh < HH);
        #pragma unroll
        for (int dx = -1; dx <= 1; dx++){
            int ww = w + dx;
            if (okh && ww >= 0 && ww < WW){
                float4 xv = *(const float4*)&g_xz[((size_t)(b*LL + hh*WW + ww))*256 + dq*4];
                float4 wt = *(const float4*)&wsh[(dy+1)*3 + (dx+1)][dq*4];
                s.x = fmaf(xv.x, wt.x, s.x);
                s.y = fmaf(xv.y, wt.y, s.y);
                s.z = fmaf(xv.z, wt.z, s.z);
                s.w = fmaf(xv.w, wt.w, s.w);
            }
        }
    }
    s.x *= fsigmoid(s.x); s.y *= fsigmoid(s.y); s.z *= fsigmoid(s.z); s.w *= fsigmoid(s.w);
    *(float4*)&g_xc[(size_t)pos*128 + dq*4] = s;

    #pragma unroll
    for (int c = 0; c < 24; c++){
        float4 wv = *(const float4*)&wp[c][dq*4];
        red[warpid][lane][c] = s.x*wv.x + s.y*wv.y + s.z*wv.z + s.w*wv.w;
    }
    __syncwarp();
    if (lane < 24){
        float outv = 0.f;
        #pragma unroll 8
        for (int i = 0; i < 32; i++) outv += red[warpid][i][lane];
        g_proj[(size_t)pos*24 + lane] = outv;
    }
}

// ---------------- K3: scan pass 1 — paired dirs, vec loads, fused combine ----------------
__global__ void __launch_bounds__(128) k_pass1(const float* __restrict__ dtw, const float* __restrict__ dtb,
                                               const float* __restrict__ alog){
    const int s = blockIdx.x, b = blockIdx.y, pair = blockIdx.z;
    const int d = threadIdx.x;
    const int kf = pair*2, kb_ = pair*2 + 1;
    float4 wf = *(const float4*)&dtw[(size_t)(kf*128 + d)*4];
    float4 wb = *(const float4*)&dtw[(size_t)(kb_*128 + d)*4];
    float bf = dtb[kf*128 + d], bbs = dtb[kb_*128 + d];
    float Af = -ex2f(alog[kf*128 + d] * LOG2E);
    float Ab = -ex2f(alog[kb_*128 + d] * LOG2E);

    float hf = 0.f, Pf = 1.f;
    float hb = 0.f, Pb = 1.f;
    #pragma unroll 2
    for (int i = 0; i < SEGLEN; i++){
        int p  = (pair == 0) ? (s*WW + i) : (i*WW + s);
        int bp = b*LL + p;
        float xcv = g_xc[(size_t)bp*128 + d];
        const float4* prp = (const float4*)&g_proj[(size_t)bp*24 + pair*12];
        float4 f0 = __ldg(prp+0);   // p0f p1f p2f p3f
        float4 f1 = __ldg(prp+1);   // Bf  Cf  p0b p1b
        float4 f2 = __ldg(prp+2);   // p2b p3b Bb  Cb
        // forward
        float xf = fmaf(wf.x, f0.x, bf);
        xf = fmaf(wf.y, f0.y, xf);
        xf = fmaf(wf.z, f0.z, xf);
        xf = fmaf(wf.w, f0.w, xf);
        float uf = sp_u(xf);
        float daf = ex2f(Af * uf);
        float dbf = uf * LN2 * f1.x * xcv;
        hf = fmaf(daf, hf, dbf);
        Pf *= daf;
        // backward (summary in forward order)
        float xb = fmaf(wb.x, f1.z, bbs);
        xb = fmaf(wb.y, f1.w, xb);
        xb = fmaf(wb.z, f2.x, xb);
        xb = fmaf(wb.w, f2.y, xb);
        float ub = sp_u(xb);
        float dab = ex2f(Ab * ub);
        float dbb = ub * LN2 * f2.z * xcv;
        hb = fmaf(dbb, Pb, hb);
        Pb *= dab;
    }
    const int gf = b*4 + kf, gb = b*4 + kb_;
    size_t if_ = ((size_t)gf*NSEG + s)*128 + d;
    size_t ib_ = ((size_t)gb*NSEG + (NSEG-1-s))*128 + d;
    g_hend[if_]  = hf;  g_aprod[if_] = Pf;
    g_hend[ib_]  = hb;  g_aprod[ib_] = Pb;

    // fused combine: last block of this (b,pair) group runs the 2-chain prefix
    __threadfence();
    __shared__ unsigned int done;
    if (d == 0) done = atomicAdd(&g_cnt[b*2 + pair], 1u);
    __syncthreads();
    if (done == NSEG - 1){
        __threadfence();
        float c1 = 0.f, c2 = 0.f;
        #pragma unroll 4
        for (int ss = 0; ss < NSEG; ss++){
            size_t i1 = ((size_t)gf*NSEG + ss)*128 + d;
            g_init[i1] = c1;
            c1 = fmaf(g_aprod[i1], c1, g_hend[i1]);
            size_t i2 = ((size_t)gb*NSEG + ss)*128 + d;
            g_init[i2] = c2;
            c2 = fmaf(g_aprod[i2], c2, g_hend[i2]);
        }
    }
}

// ---------------- K4: scan pass 2 — both pairs concurrent, vec loads ----------------
__global__ void __launch_bounds__(128) k_pass2(const float* __restrict__ dtw, const float* __restrict__ dtb,
                                               const float* __restrict__ alog, const float* __restrict__ Ds){
    __shared__ float ybuf[SEGLEN][128];
    const int s = blockIdx.x, b = blockIdx.y, pair = blockIdx.z;
    const int d = threadIdx.x;
    const int kf = pair*2, kb_ = pair*2 + 1;
    float4 wf = *(const float4*)&dtw[(size_t)(kf*128 + d)*4];
    float4 wb = *(const float4*)&dtw[(size_t)(kb_*128 + d)*4];
    float bf = dtb[kf*128 + d], bbs = dtb[kb_*128 + d];
    float Af = -ex2f(alog[kf*128 + d] * LOG2E);
    float Ab = -ex2f(alog[kb_*128 + d] * LOG2E);
    const int gf = b*4 + kf, gb = b*4 + kb_;

    // backward direction: descending traversal of this segment
    float hb = g_init[((size_t)gb*NSEG + (NSEG-1-s))*128 + d];
    #pragma unroll 2
    for (int i = SEGLEN-1; i >= 0; i--){
        int p  = (pair == 0) ? (s*WW + i) : (i*WW + s);
        int bp = b*LL + p;
        float xcv = g_xc[(size_t)bp*128 + d];
        const float* prb = &g_proj[(size_t)bp*24 + pair*12];
        float2 g1 = __ldg((const float2*)(prb + 6));   // p0b p1b
        float4 g2 = __ldg((const float4*)(prb + 8));   // p2b p3b Bb Cb
        float xb = fmaf(wb.x, g1.x, bbs);
        xb = fmaf(wb.y, g1.y, xb);
        xb = fmaf(wb.z, g2.x, xb);
        xb = fmaf(wb.w, g2.y, xb);
        float ub = sp_u(xb);
        float dab = ex2f(Ab * ub);
        float dbb = ub * LN2 * g2.z * xcv;
        hb = fmaf(dab, hb, dbb);
        ybuf[i][d] = hb * g2.w;
    }
    // forward direction + merge
    float sumDs = Ds[d] + Ds[128+d] + Ds[256+d] + Ds[384+d];
    float hf = g_init[((size_t)gf*NSEG + s)*128 + d];
    #pragma unroll 2
    for (int i = 0; i < SEGLEN; i++){
        int p  = (pair == 0) ? (s*WW + i) : (i*WW + s);
        int bp = b*LL + p;
        float xcv = g_xc[(size_t)bp*128 + d];
        const float* prb = &g_proj[(size_t)bp*24 + pair*12];
        float4 f0 = __ldg((const float4*)prb);         // p0f p1f p2f p3f
        float2 f1 = __ldg((const float2*)(prb + 4));   // Bf Cf
        float xf = fmaf(wf.x, f0.x, bf);
        xf = fmaf(wf.y, f0.y, xf);
        xf = fmaf(wf.z, f0.z, xf);
        xf = fmaf(wf.w, f0.w, xf);
        float uf = sp_u(xf);
        float daf = ex2f(Af * uf);
        float dbf = uf * LN2 * f1.x * xcv;
        hf = fmaf(daf, hf, dbf);
        float val = fmaf(hf, f1.y, ybuf[i][d]);
        if (pair == 0){
            g_ysum[(size_t)bp*128 + d] = fmaf(xcv, sumDs, val);
        } else {
            g_ysum2[(size_t)bp*128 + d] = val;
        }
    }
}

// ---------------- K5: LayerNorm + SiLU gate + spatial mean ----------------
__global__ void __launch_bounds__(256) k_final(const float* __restrict__ nw, const float* __restrict__ nb,
                                               float* __restrict__ out){
    const int b = blockIdx.y;
    const int t = threadIdx.x;
    const int warp = t >> 5, lane = t & 31;
    const int d4 = lane*4;
    float4 w4 = *(const float4*)&nw[d4];
    float4 b4 = *(const float4*)&nb[d4];

    float4 acc = make_float4(0.f,0.f,0.f,0.f);
    #pragma unroll 2
    for (int j = 0; j < 8; j++){
        int p = blockIdx.x*64 + warp*8 + j;
        size_t base = ((size_t)(b*LL + p))*128 + d4;
        float4 v  = *(const float4*)&g_ysum[base];
        float4 v2 = *(const float4*)&g_ysum2[base];
        v.x += v2.x; v.y += v2.y; v.z += v2.z; v.w += v2.w;
        float sm = v.x+v.y+v.z+v.w;
        #pragma unroll
        for (int o = 16; o > 0; o >>= 1) sm += __shfl_xor_sync(~0u, sm, o);
        float mu = sm * (1.f/128.f);
        float4 dv = make_float4(v.x-mu, v.y-mu, v.z-mu, v.w-mu);
        float s2 = dv.x*dv.x + dv.y*dv.y + dv.z*dv.z + dv.w*dv.w;
        #pragma unroll
        for (int o = 16; o > 0; o >>= 1) s2 += __shfl_xor_sync(~0u, s2, o);
        float rstd = rsqrtf(s2 * (1.f/128.f) + 1e-5f);
        float4 z = *(const float4*)&g_xz[((size_t)(b*LL + p))*256 + 128 + d4];
        float gx = z.x*fsigmoid(z.x), gy = z.y*fsigmoid(z.y);
        float gz = z.z*fsigmoid(z.z), gw = z.w*fsigmoid(z.w);
        acc.x = fmaf(fmaf(dv.x*rstd, w4.x, b4.x), gx, acc.x);
        acc.y = fmaf(fmaf(dv.y*rstd, w4.y, b4.y), gy, acc.y);
        acc.z = fmaf(fmaf(dv.z*rstd, w4.z, b4.z), gz, acc.z);
        acc.w = fmaf(fmaf(dv.w*rstd, w4.w, b4.w), gw, acc.w);
    }
    const float sc = 1.f/(float)LL;
    atomicAdd(&out[b*128 + d4 + 0], acc.x*sc);
    atomicAdd(&out[b*128 + d4 + 1], acc.y*sc);
    atomicAdd(&out[b*128 + d4 + 2], acc.z*sc);
    atomicAdd(&out[b*128 + d4 + 3], acc.w*sc);
}

// ---------------- launch ----------------
extern "C" void kernel_launch(void* const* d_in, const int* in_sizes, int n_in,
                              void* d_out, int out_size){
    const float* x    = (const float*)d_in[0];
    const float* inw  = (const float*)d_in[1];
    const float* cw   = (const float*)d_in[2];
    const float* cb   = (const float*)d_in[3];
    const float* xpw  = (const float*)d_in[4];
    const float* dtw  = (const float*)d_in[5];
    const float* dtb  = (const float*)d_in[6];
    const float* alog = (const float*)d_in[7];
    const float* Ds   = (const float*)d_in[8];
    const float* onw  = (const float*)d_in[9];
    const float* onb  = (const float*)d_in[10];
    float* out = (float*)d_out;

    k_zero<<<(BB*DD + 255)/256, 256>>>(out);
    k_gemm<<<dim3((BB*LL)/128, 4), 256>>>(x, inw);
    k_convp<<<(BB*LL)/8, 256>>>(cw, cb, xpw);
    k_pass1<<<dim3(NSEG, BB, 2), 128>>>(dtw, dtb, alog);
    k_pass2<<<dim3(NSEG, BB, 2), 128>>>(dtw, dtb, alog, Ds);
    k_final<<<dim3(LL/64, BB), 256>>>(onw, onb, out);
}

// round 6
// speedup vs baseline: 7.6651x; 1.0311x over previous
#include <cuda_runtime.h>
#include <cuda_bf16.h>
#include <cstdint>

// ---------------- problem constants ----------------
#define BB 16
#define HH 56
#define WW 56
#define LL (HH*WW)      // 3136
#define DD 128
#define KK 4
#define NSEG 112
#define SEGLEN 28       // 112*28 = 3136

#define LOG2E 1.4426950408889634f
#define LN2   0.6931471805599453f

// ---------------- scratch (device globals; no allocs allowed) ----------------
__device__ float g_xz   [(size_t)BB*LL*256];     // in_proj output (xi | z), channel-last
__device__ float g_xc   [(size_t)BB*LL*DD];      // conv+silu output, channel-last
__device__ float g_proj [(size_t)BB*LL*24];      // x_dbl: per pos, [k*6 + c]
__device__ float g_ysum [(size_t)BB*LL*DD];      // pair01 y + Ds*xc
__device__ float g_ysum2[(size_t)BB*LL*DD];      // pair23 y
__device__ float g_hend [(size_t)64*NSEG*DD];
__device__ float g_aprod[(size_t)64*NSEG*DD];
__device__ float g_init [(size_t)64*NSEG*DD];

// ---------------- math helpers (MUFU) ----------------
__device__ __forceinline__ float ex2f(float x){ float y; asm("ex2.approx.ftz.f32 %0,%1;" : "=f"(y) : "f"(x)); return y; }
__device__ __forceinline__ float lg2f(float x){ float y; asm("lg2.approx.ftz.f32 %0,%1;" : "=f"(y) : "f"(x)); return y; }
__device__ __forceinline__ float rcpf(float x){ float y; asm("rcp.approx.ftz.f32 %0,%1;" : "=f"(y) : "f"(x)); return y; }
__device__ __forceinline__ float fsigmoid(float x){ return rcpf(1.f + ex2f(-x*LOG2E)); }

// softplus in log2 domain: returns u = softplus(x)*log2e
__device__ __forceinline__ float sp_u(float x){
    float tt = ex2f(fminf(x, 20.f) * LOG2E);
    return (x > 20.f) ? x * LOG2E : lg2f(1.f + tt);
}

// position for scan step: pair0 row-major, pair1 column-major
__device__ __forceinline__ int scan_pos(int pair, int s, int i){
    return (pair == 0) ? ((s>>1)*WW + (s&1)*SEGLEN + i)
                       : (((s&1)*SEGLEN + i)*WW + (s>>1));
}

// ---------------- K0: zero d_out ----------------
__global__ void k_zero(float* out){
    int i = blockIdx.x*blockDim.x + threadIdx.x;
    if (i < BB*DD) out[i] = 0.f;
}

// ---------------- tensor-core GEMM helpers ----------------
__device__ __forceinline__ void ldsm4(uint32_t* r, uint32_t addr){
    asm volatile("ldmatrix.sync.aligned.m8n8.x4.shared.b16 {%0,%1,%2,%3}, [%4];"
        : "=r"(r[0]),"=r"(r[1]),"=r"(r[2]),"=r"(r[3]) : "r"(addr));
}
__device__ __forceinline__ void mma16816(float* c, const uint32_t* a, const uint32_t* b){
    asm volatile("mma.sync.aligned.m16n8k16.row.col.f32.bf16.bf16.f32 "
        "{%0,%1,%2,%3}, {%4,%5,%6,%7}, {%8,%9}, {%0,%1,%2,%3};"
        : "+f"(c[0]),"+f"(c[1]),"+f"(c[2]),"+f"(c[3])
        : "r"(a[0]),"r"(a[1]),"r"(a[2]),"r"(a[3]), "r"(b[0]),"r"(b[1]));
}
__device__ __forceinline__ uint32_t pkbf(__nv_bfloat162 h){ return *reinterpret_cast<uint32_t*>(&h); }

// ---------------- K1: in_proj GEMM (M=50176,N=256,K=128) bf16 split-precision MMA -------
__global__ void __launch_bounds__(256) k_gemm(const float* __restrict__ X, const float* __restrict__ Wm){
    __shared__ __align__(16) __nv_bfloat16 sA[2][128][40];
    __shared__ uint32_t sB[2][64][18];
    const int t = threadIdx.x;
    const int row0 = blockIdx.x * 128;
    const int col0 = blockIdx.y * 64;
    const int wid = t >> 5, lane = t & 31;
    const int mw = wid & 3, nw = wid >> 2;
    float acc[2][4][4] = {};

    for (int kb = 0; kb < 128; kb += 32){
        #pragma unroll
        for (int j = 0; j < 4; j++){
            int fid = t + j*256;
            int r = fid >> 3, kq = (fid & 7) << 2;
            float4 v = *(const float4*)&X[(size_t)(row0+r)*128 + kb + kq];
            __nv_bfloat162 h01 = __floats2bfloat162_rn(v.x, v.y);
            __nv_bfloat162 h23 = __floats2bfloat162_rn(v.z, v.w);
            float2 f01 = __bfloat1622float2(h01);
            float2 f23 = __bfloat1622float2(h23);
            *(__nv_bfloat162*)&sA[0][r][kq]   = h01;
            *(__nv_bfloat162*)&sA[0][r][kq+2] = h23;
            *(__nv_bfloat162*)&sA[1][r][kq]   = __floats2bfloat162_rn(v.x - f01.x, v.y - f01.y);
            *(__nv_bfloat162*)&sA[1][r][kq+2] = __floats2bfloat162_rn(v.z - f23.x, v.w - f23.y);
        }
        #pragma unroll
        for (int j = 0; j < 2; j++){
            int fid = t + j*256;
            int r = fid >> 3, kq = (fid & 7) << 2;
            float4 v = *(const float4*)&Wm[(size_t)(col0+r)*128 + kb + kq];
            __nv_bfloat162 h01 = __floats2bfloat162_rn(v.x, v.y);
            __nv_bfloat162 h23 = __floats2bfloat162_rn(v.z, v.w);
            float2 f01 = __bfloat1622float2(h01);
            float2 f23 = __bfloat1622float2(h23);
            sB[0][r][(kq>>1)  ] = pkbf(h01);
            sB[0][r][(kq>>1)+1] = pkbf(h23);
            sB[1][r][(kq>>1)  ] = pkbf(__floats2bfloat162_rn(v.x - f01.x, v.y - f01.y));
            sB[1][r][(kq>>1)+1] = pkbf(__floats2bfloat162_rn(v.z - f23.x, v.w - f23.y));
        }
        __syncthreads();
        #pragma unroll
        for (int ks = 0; ks < 2; ks++){
            uint32_t ah[2][4], al[2][4];
            #pragma unroll
            for (int f = 0; f < 2; f++){
                int rr = mw*32 + f*16 + (lane & 15);
                int cc = ks*16 + (lane >> 4)*8;
                ldsm4(ah[f], (uint32_t)__cvta_generic_to_shared(&sA[0][rr][cc]));
                ldsm4(al[f], (uint32_t)__cvta_generic_to_shared(&sA[1][rr][cc]));
            }
            #pragma unroll
            for (int j = 0; j < 4; j++){
                int nr = nw*32 + j*8 + (lane >> 2);
                int kp = ks*8 + (lane & 3);
                uint32_t bh[2] = { sB[0][nr][kp], sB[0][nr][kp+4] };
                uint32_t bl[2] = { sB[1][nr][kp], sB[1][nr][kp+4] };
                #pragma unroll
                for (int f = 0; f < 2; f++){
                    mma16816(acc[f][j], ah[f], bh);
                    mma16816(acc[f][j], ah[f], bl);
                    mma16816(acc[f][j], al[f], bh);
                }
            }
        }
        __syncthreads();
    }
    #pragma unroll
    for (int f = 0; f < 2; f++){
        #pragma unroll
        for (int j = 0; j < 4; j++){
            int r = row0 + mw*32 + f*16 + (lane >> 2);
            int c = col0 + nw*32 + j*8 + (lane & 3)*2;
            *(float2*)&g_xz[(size_t)r*256 + c]     = make_float2(acc[f][j][0], acc[f][j][1]);
            *(float2*)&g_xz[(size_t)(r+8)*256 + c] = make_float2(acc[f][j][2], acc[f][j][3]);
        }
    }
}

// ---------------- K2: depthwise conv + SiLU + fused x_dbl (warp-per-position) -------------
__global__ void __launch_bounds__(256) k_convp(const float* __restrict__ cw, const float* __restrict__ cb,
                                               const float* __restrict__ xpw){
    __shared__ float wsh[9][128];
    __shared__ float bsh[128];
    __shared__ float wp[24][132];
    __shared__ float red[8][32][25];
    const int t = threadIdx.x;
    for (int i = t; i < 1152; i += 256) wsh[i % 9][i / 9] = cw[i];
    if (t < 128) bsh[t] = cb[t];
    for (int i = t; i < 24*128; i += 256) wp[i>>7][i&127] = xpw[i];
    __syncthreads();

    const int lane = t & 31;
    const int warpid = t >> 5;
    const int dq = lane;
    int pos = blockIdx.x*8 + warpid;
    int rest = pos;
    int w = rest % WW; rest /= WW;
    int h = rest % HH;
    int b = rest / HH;

    float4 s = *(const float4*)&bsh[dq*4];
    #pragma unroll
    for (int dy = -1; dy <= 1; dy++){
        int hh = h + dy;
        bool okh = (hh >= 0) && (hh < HH);
        #pragma unroll
        for (int dx = -1; dx <= 1; dx++){
            int ww = w + dx;
            if (okh && ww >= 0 && ww < WW){
                float4 xv = *(const float4*)&g_xz[((size_t)(b*LL + hh*WW + ww))*256 + dq*4];
                float4 wt = *(const float4*)&wsh[(dy+1)*3 + (dx+1)][dq*4];
                s.x = fmaf(xv.x, wt.x, s.x);
                s.y = fmaf(xv.y, wt.y, s.y);
                s.z = fmaf(xv.z, wt.z, s.z);
                s.w = fmaf(xv.w, wt.w, s.w);
            }
        }
    }
    s.x *= fsigmoid(s.x); s.y *= fsigmoid(s.y); s.z *= fsigmoid(s.z); s.w *= fsigmoid(s.w);
    *(float4*)&g_xc[(size_t)pos*128 + dq*4] = s;

    #pragma unroll
    for (int c = 0; c < 24; c++){
        float4 wv = *(const float4*)&wp[c][dq*4];
        red[warpid][lane][c] = s.x*wv.x + s.y*wv.y + s.z*wv.z + s.w*wv.w;
    }
    __syncwarp();
    if (lane < 24){
        float outv = 0.f;
        #pragma unroll 8
        for (int i = 0; i < 32; i++) outv += red[warpid][i][lane];
        g_proj[(size_t)pos*24 + lane] = outv;
    }
}

// ---------------- K3: scan pass 1 — paired dirs, vec loads ----------------
__global__ void __launch_bounds__(128) k_pass1(const float* __restrict__ dtw, const float* __restrict__ dtb,
                                               const float* __restrict__ alog){
    const int s = blockIdx.x, b = blockIdx.y, pair = blockIdx.z;
    const int d = threadIdx.x;
    const int kf = pair*2, kb_ = pair*2 + 1;
    float4 wf = *(const float4*)&dtw[(size_t)(kf*128 + d)*4];
    float4 wb = *(const float4*)&dtw[(size_t)(kb_*128 + d)*4];
    float bf = dtb[kf*128 + d], bbs = dtb[kb_*128 + d];
    float Af = -ex2f(alog[kf*128 + d] * LOG2E);
    float Ab = -ex2f(alog[kb_*128 + d] * LOG2E);

    float hf = 0.f, Pf = 1.f;
    float hb = 0.f, Pb = 1.f;
    #pragma unroll 2
    for (int i = 0; i < SEGLEN; i++){
        int bp = b*LL + scan_pos(pair, s, i);
        float xcv = g_xc[(size_t)bp*128 + d];
        const float4* prp = (const float4*)&g_proj[(size_t)bp*24 + pair*12];
        float4 f0 = __ldg(prp+0);   // p0f p1f p2f p3f
        float4 f1 = __ldg(prp+1);   // Bf  Cf  p0b p1b
        float4 f2 = __ldg(prp+2);   // p2b p3b Bb  Cb
        // forward
        float xf = fmaf(wf.x, f0.x, bf);
        xf = fmaf(wf.y, f0.y, xf);
        xf = fmaf(wf.z, f0.z, xf);
        xf = fmaf(wf.w, f0.w, xf);
        float uf = sp_u(xf);
        float daf = ex2f(Af * uf);
        float dbf = uf * LN2 * f1.x * xcv;
        hf = fmaf(daf, hf, dbf);
        Pf *= daf;
        // backward (summary in forward order)
        float xb = fmaf(wb.x, f1.z, bbs);
        xb = fmaf(wb.y, f1.w, xb);
        xb = fmaf(wb.z, f2.x, xb);
        xb = fmaf(wb.w, f2.y, xb);
        float ub = sp_u(xb);
        float dab = ex2f(Ab * ub);
        float dbb = ub * LN2 * f2.z * xcv;
        hb = fmaf(dbb, Pb, hb);
        Pb *= dab;
    }
    const int gf = b*4 + kf, gb = b*4 + kb_;
    size_t if_ = ((size_t)gf*NSEG + s)*128 + d;
    size_t ib_ = ((size_t)gb*NSEG + (NSEG-1-s))*128 + d;
    g_hend[if_]  = hf;  g_aprod[if_] = Pf;
    g_hend[ib_]  = hb;  g_aprod[ib_] = Pb;
}

// ---------------- K4: combine (prefix over segments, per scan-chain) ----------------
__global__ void k_comb(){
    const int g = blockIdx.x, d = threadIdx.x;
    float carry = 0.f;
    #pragma unroll 8
    for (int s = 0; s < NSEG; s++){
        size_t idx = ((size_t)g*NSEG + s)*128 + d;
        g_init[idx] = carry;
        carry = fmaf(g_aprod[idx], carry, g_hend[idx]);
    }
}

// ---------------- K5: scan pass 2 — both pairs concurrent, vec loads ----------------
__global__ void __launch_bounds__(128) k_pass2(const float* __restrict__ dtw, const float* __restrict__ dtb,
                                               const float* __restrict__ alog, const float* __restrict__ Ds){
    __shared__ float ybuf[SEGLEN][128];
    const int s = blockIdx.x, b = blockIdx.y, pair = blockIdx.z;
    const int d = threadIdx.x;
    const int kf = pair*2, kb_ = pair*2 + 1;
    float4 wf = *(const float4*)&dtw[(size_t)(kf*128 + d)*4];
    float4 wb = *(const float4*)&dtw[(size_t)(kb_*128 + d)*4];
    float bf = dtb[kf*128 + d], bbs = dtb[kb_*128 + d];
    float Af = -ex2f(alog[kf*128 + d] * LOG2E);
    float Ab = -ex2f(alog[kb_*128 + d] * LOG2E);
    const int gf = b*4 + kf, gb = b*4 + kb_;

    // backward direction: descending traversal of this segment
    float hb = g_init[((size_t)gb*NSEG + (NSEG-1-s))*128 + d];
    #pragma unroll 2
    for (int i = SEGLEN-1; i >= 0; i--){
        int bp = b*LL + scan_pos(pair, s, i);
        float xcv = g_xc[(size_t)bp*128 + d];
        const float* prb = &g_proj[(size_t)bp*24 + pair*12];
        float2 g1 = __ldg((const float2*)(prb + 6));   // p0b p1b
        float4 g2 = __ldg((const float4*)(prb + 8));   // p2b p3b Bb Cb
        float xb = fmaf(wb.x, g1.x, bbs);
        xb = fmaf(wb.y, g1.y, xb);
        xb = fmaf(wb.z, g2.x, xb);
        xb = fmaf(wb.w, g2.y, xb);
        float ub = sp_u(xb);
        float dab = ex2f(Ab * ub);
        float dbb = ub * LN2 * g2.z * xcv;
        hb = fmaf(dab, hb, dbb);
        ybuf[i][d] = hb * g2.w;
    }
    // forward direction + merge
    float sumDs = Ds[d] + Ds[128+d] + Ds[256+d] + Ds[384+d];
    float hf = g_init[((size_t)gf*NSEG + s)*128 + d];
    #pragma unroll 2
    for (int i = 0; i < SEGLEN; i++){
        int bp = b*LL + scan_pos(pair, s, i);
        float xcv = g_xc[(size_t)bp*128 + d];
        const float* prb = &g_proj[(size_t)bp*24 + pair*12];
        float4 f0 = __ldg((const float4*)prb);         // p0f p1f p2f p3f
        float2 f1 = __ldg((const float2*)(prb + 4));   // Bf Cf
        float xf = fmaf(wf.x, f0.x, bf);
        xf = fmaf(wf.y, f0.y, xf);
        xf = fmaf(wf.z, f0.z, xf);
        xf = fmaf(wf.w, f0.w, xf);
        float uf = sp_u(xf);
        float daf = ex2f(Af * uf);
        float dbf = uf * LN2 * f1.x * xcv;
        hf = fmaf(daf, hf, dbf);
        float val = fmaf(hf, f1.y, ybuf[i][d]);
        if (pair == 0){
            g_ysum[(size_t)bp*128 + d] = fmaf(xcv, sumDs, val);
        } else {
            g_ysum2[(size_t)bp*128 + d] = val;
        }
    }
}

// ---------------- K6: LayerNorm + SiLU gate + spatial mean ----------------
__global__ void __launch_bounds__(256) k_final(const float* __restrict__ nw, const float* __restrict__ nb,
                                               float* __restrict__ out){
    const int b = blockIdx.y;
    const int t = threadIdx.x;
    const int warp = t >> 5, lane = t & 31;
    const int d4 = lane*4;
    float4 w4 = *(const float4*)&nw[d4];
    float4 b4 = *(const float4*)&nb[d4];

    float4 acc = make_float4(0.f,0.f,0.f,0.f);
    #pragma unroll 2
    for (int j = 0; j < 8; j++){
        int p = blockIdx.x*64 + warp*8 + j;
        size_t base = ((size_t)(b*LL + p))*128 + d4;
        float4 v  = *(const float4*)&g_ysum[base];
        float4 v2 = *(const float4*)&g_ysum2[base];
        v.x += v2.x; v.y += v2.y; v.z += v2.z; v.w += v2.w;
        float sm = v.x+v.y+v.z+v.w;
        #pragma unroll
        for (int o = 16; o > 0; o >>= 1) sm += __shfl_xor_sync(~0u, sm, o);
        float mu = sm * (1.f/128.f);
        float4 dv = make_float4(v.x-mu, v.y-mu, v.z-mu, v.w-mu);
        float s2 = dv.x*dv.x + dv.y*dv.y + dv.z*dv.z + dv.w*dv.w;
        #pragma unroll
        for (int o = 16; o > 0; o >>= 1) s2 += __shfl_xor_sync(~0u, s2, o);
        float rstd = rsqrtf(s2 * (1.f/128.f) + 1e-5f);
        float4 z = *(const float4*)&g_xz[((size_t)(b*LL + p))*256 + 128 + d4];
        float gx = z.x*fsigmoid(z.x), gy = z.y*fsigmoid(z.y);
        float gz = z.z*fsigmoid(z.z), gw = z.w*fsigmoid(z.w);
        acc.x = fmaf(fmaf(dv.x*rstd, w4.x, b4.x), gx, acc.x);
        acc.y = fmaf(fmaf(dv.y*rstd, w4.y, b4.y), gy, acc.y);
        acc.z = fmaf(fmaf(dv.z*rstd, w4.z, b4.z), gz, acc.z);
        acc.w = fmaf(fmaf(dv.w*rstd, w4.w, b4.w), gw, acc.w);
    }
    const float sc = 1.f/(float)LL;
    atomicAdd(&out[b*128 + d4 + 0], acc.x*sc);
    atomicAdd(&out[b*128 + d4 + 1], acc.y*sc);
    atomicAdd(&out[b*128 + d4 + 2], acc.z*sc);
    atomicAdd(&out[b*128 + d4 + 3], acc.w*sc);
}

// ---------------- launch ----------------
extern "C" void kernel_launch(void* const* d_in, const int* in_sizes, int n_in,
                              void* d_out, int out_size){
    const float* x    = (const float*)d_in[0];
    const float* inw  = (const float*)d_in[1];
    const float* cw   = (const float*)d_in[2];
    const float* cb   = (const float*)d_in[3];
    const float* xpw  = (const float*)d_in[4];
    const float* dtw  = (const float*)d_in[5];
    const float* dtb  = (const float*)d_in[6];
    const float* alog = (const float*)d_in[7];
    const float* Ds   = (const float*)d_in[8];
    const float* onw  = (const float*)d_in[9];
    const float* onb  = (const float*)d_in[10];
    float* out = (float*)d_out;

    k_zero<<<(BB*DD + 255)/256, 256>>>(out);
    k_gemm<<<dim3((BB*LL)/128, 4), 256>>>(x, inw);
    k_convp<<<(BB*LL)/8, 256>>>(cw, cb, xpw);
    k_pass1<<<dim3(NSEG, BB, 2), 128>>>(dtw, dtb, alog);
    k_comb<<<64, 128>>>();
    k_pass2<<<dim3(NSEG, BB, 2), 128>>>(dtw, dtb, alog, Ds);
    k_final<<<dim3(LL/64, BB), 256>>>(onw, onb, out);
}

// round 7
// speedup vs baseline: 7.9751x; 1.0404x over previous
#include <cuda_runtime.h>
#include <cuda_bf16.h>
#include <cstdint>

// ---------------- problem constants ----------------
#define BB 16
#define HH 56
#define WW 56
#define LL (HH*WW)      // 3136
#define DD 128
#define KK 4
#define NSEG 112
#define SEGLEN 28       // 112*28 = 3136

#define LOG2E 1.4426950408889634f
#define LN2   0.6931471805599453f

// ---------------- scratch (device globals; no allocs allowed) ----------------
__device__ float g_xz   [(size_t)BB*LL*256];     // in_proj output (xi | z), channel-last
__device__ float g_xc   [(size_t)BB*LL*DD];      // conv+silu output, channel-last
__device__ float g_proj [(size_t)BB*LL*24];      // x_dbl: per pos, [k*6 + c]
__device__ float g_ysum [(size_t)BB*LL*DD];      // pair01 y + Ds*xc
__device__ float g_ysum2[(size_t)BB*LL*DD];      // pair23 y
__device__ float g_hend [(size_t)64*NSEG*DD];
__device__ float g_aprod[(size_t)64*NSEG*DD];
__device__ float g_init [(size_t)64*NSEG*DD];

// ---------------- math helpers (MUFU) ----------------
__device__ __forceinline__ float ex2f(float x){ float y; asm("ex2.approx.ftz.f32 %0,%1;" : "=f"(y) : "f"(x)); return y; }
__device__ __forceinline__ float lg2f(float x){ float y; asm("lg2.approx.ftz.f32 %0,%1;" : "=f"(y) : "f"(x)); return y; }
__device__ __forceinline__ float rcpf(float x){ float y; asm("rcp.approx.ftz.f32 %0,%1;" : "=f"(y) : "f"(x)); return y; }
__device__ __forceinline__ float fsigmoid(float x){ return rcpf(1.f + ex2f(-x*LOG2E)); }

// softplus in log2 domain: returns u = softplus(x)*log2e
__device__ __forceinline__ float sp_u(float x){
    float tt = ex2f(fminf(x, 20.f) * LOG2E);
    return (x > 20.f) ? x * LOG2E : lg2f(1.f + tt);
}

// position for scan step: pair0 row-major, pair1 column-major
__device__ __forceinline__ int scan_pos(int pair, int s, int i){
    return (pair == 0) ? ((s>>1)*WW + (s&1)*SEGLEN + i)
                       : (((s&1)*SEGLEN + i)*WW + (s>>1));
}

// ---------------- K0: zero d_out ----------------
__global__ void k_zero(float* out){
    int i = blockIdx.x*blockDim.x + threadIdx.x;
    if (i < BB*DD) out[i] = 0.f;
}

// ---------------- tensor-core GEMM helpers ----------------
__device__ __forceinline__ void ldsm4(uint32_t* r, uint32_t addr){
    asm volatile("ldmatrix.sync.aligned.m8n8.x4.shared.b16 {%0,%1,%2,%3}, [%4];"
        : "=r"(r[0]),"=r"(r[1]),"=r"(r[2]),"=r"(r[3]) : "r"(addr));
}
__device__ __forceinline__ void mma16816(float* c, const uint32_t* a, const uint32_t* b){
    asm volatile("mma.sync.aligned.m16n8k16.row.col.f32.bf16.bf16.f32 "
        "{%0,%1,%2,%3}, {%4,%5,%6,%7}, {%8,%9}, {%0,%1,%2,%3};"
        : "+f"(c[0]),"+f"(c[1]),"+f"(c[2]),"+f"(c[3])
        : "r"(a[0]),"r"(a[1]),"r"(a[2]),"r"(a[3]), "r"(b[0]),"r"(b[1]));
}
__device__ __forceinline__ uint32_t pkbf(__nv_bfloat162 h){ return *reinterpret_cast<uint32_t*>(&h); }

// ---------------- K1: in_proj GEMM (M=50176,N=256,K=128) bf16 split-precision MMA -------
__global__ void __launch_bounds__(256) k_gemm(const float* __restrict__ X, const float* __restrict__ Wm){
    __shared__ __align__(16) __nv_bfloat16 sA[2][128][40];
    __shared__ uint32_t sB[2][64][18];
    const int t = threadIdx.x;
    const int row0 = blockIdx.x * 128;
    const int col0 = blockIdx.y * 64;
    const int wid = t >> 5, lane = t & 31;
    const int mw = wid & 3, nw = wid >> 2;
    float acc[2][4][4] = {};

    for (int kb = 0; kb < 128; kb += 32){
        #pragma unroll
        for (int j = 0; j < 4; j++){
            int fid = t + j*256;
            int r = fid >> 3, kq = (fid & 7) << 2;
            float4 v = *(const float4*)&X[(size_t)(row0+r)*128 + kb + kq];
            __nv_bfloat162 h01 = __floats2bfloat162_rn(v.x, v.y);
            __nv_bfloat162 h23 = __floats2bfloat162_rn(v.z, v.w);
            float2 f01 = __bfloat1622float2(h01);
            float2 f23 = __bfloat1622float2(h23);
            *(__nv_bfloat162*)&sA[0][r][kq]   = h01;
            *(__nv_bfloat162*)&sA[0][r][kq+2] = h23;
            *(__nv_bfloat162*)&sA[1][r][kq]   = __floats2bfloat162_rn(v.x - f01.x, v.y - f01.y);
            *(__nv_bfloat162*)&sA[1][r][kq+2] = __floats2bfloat162_rn(v.z - f23.x, v.w - f23.y);
        }
        #pragma unroll
        for (int j = 0; j < 2; j++){
            int fid = t + j*256;
            int r = fid >> 3, kq = (fid & 7) << 2;
            float4 v = *(const float4*)&Wm[(size_t)(col0+r)*128 + kb + kq];
            __nv_bfloat162 h01 = __floats2bfloat162_rn(v.x, v.y);
            __nv_bfloat162 h23 = __floats2bfloat162_rn(v.z, v.w);
            float2 f01 = __bfloat1622float2(h01);
            float2 f23 = __bfloat1622float2(h23);
            sB[0][r][(kq>>1)  ] = pkbf(h01);
            sB[0][r][(kq>>1)+1] = pkbf(h23);
            sB[1][r][(kq>>1)  ] = pkbf(__floats2bfloat162_rn(v.x - f01.x, v.y - f01.y));
            sB[1][r][(kq>>1)+1] = pkbf(__floats2bfloat162_rn(v.z - f23.x, v.w - f23.y));
        }
        __syncthreads();
        #pragma unroll
        for (int ks = 0; ks < 2; ks++){
            uint32_t ah[2][4], al[2][4];
            #pragma unroll
            for (int f = 0; f < 2; f++){
                int rr = mw*32 + f*16 + (lane & 15);
                int cc = ks*16 + (lane >> 4)*8;
                ldsm4(ah[f], (uint32_t)__cvta_generic_to_shared(&sA[0][rr][cc]));
                ldsm4(al[f], (uint32_t)__cvta_generic_to_shared(&sA[1][rr][cc]));
            }
            #pragma unroll
            for (int j = 0; j < 4; j++){
                int nr = nw*32 + j*8 + (lane >> 2);
                int kp = ks*8 + (lane & 3);
                uint32_t bh[2] = { sB[0][nr][kp], sB[0][nr][kp+4] };
                uint32_t bl[2] = { sB[1][nr][kp], sB[1][nr][kp+4] };
                #pragma unroll
                for (int f = 0; f < 2; f++){
                    mma16816(acc[f][j], ah[f], bh);
                    mma16816(acc[f][j], ah[f], bl);
                    mma16816(acc[f][j], al[f], bh);
                }
            }
        }
        __syncthreads();
    }
    #pragma unroll
    for (int f = 0; f < 2; f++){
        #pragma unroll
        for (int j = 0; j < 4; j++){
            int r = row0 + mw*32 + f*16 + (lane >> 2);
            int c = col0 + nw*32 + j*8 + (lane & 3)*2;
            *(float2*)&g_xz[(size_t)r*256 + c]     = make_float2(acc[f][j][0], acc[f][j][1]);
            *(float2*)&g_xz[(size_t)(r+8)*256 + c] = make_float2(acc[f][j][2], acc[f][j][3]);
        }
    }
}

// ---------------- K2: depthwise conv + SiLU + fused x_dbl (warp-per-position) -------------
__global__ void __launch_bounds__(256) k_convp(const float* __restrict__ cw, const float* __restrict__ cb,
                                               const float* __restrict__ xpw){
    __shared__ float wsh[9][128];
    __shared__ float bsh[128];
    __shared__ float wp[24][132];
    __shared__ float red[8][32][25];
    const int t = threadIdx.x;
    for (int i = t; i < 1152; i += 256) wsh[i % 9][i / 9] = cw[i];
    if (t < 128) bsh[t] = cb[t];
    for (int i = t; i < 24*128; i += 256) wp[i>>7][i&127] = xpw[i];
    __syncthreads();

    const int lane = t & 31;
    const int warpid = t >> 5;
    const int dq = lane;
    int pos = blockIdx.x*8 + warpid;
    int rest = pos;
    int w = rest % WW; rest /= WW;
    int h = rest % HH;
    int b = rest / HH;

    float4 s = *(const float4*)&bsh[dq*4];
    #pragma unroll
    for (int dy = -1; dy <= 1; dy++){
        int hh = h + dy;
        bool okh = (hh >= 0) && (hh < HH);
        #pragma unroll
        for (int dx = -1; dx <= 1; dx++){
            int ww = w + dx;
            if (okh && ww >= 0 && ww < WW){
                float4 xv = *(const float4*)&g_xz[((size_t)(b*LL + hh*WW + ww))*256 + dq*4];
                float4 wt = *(const float4*)&wsh[(dy+1)*3 + (dx+1)][dq*4];
                s.x = fmaf(xv.x, wt.x, s.x);
                s.y = fmaf(xv.y, wt.y, s.y);
                s.z = fmaf(xv.z, wt.z, s.z);
                s.w = fmaf(xv.w, wt.w, s.w);
            }
        }
    }
    s.x *= fsigmoid(s.x); s.y *= fsigmoid(s.y); s.z *= fsigmoid(s.z); s.w *= fsigmoid(s.w);
    *(float4*)&g_xc[(size_t)pos*128 + dq*4] = s;

    #pragma unroll
    for (int c = 0; c < 24; c++){
        float4 wv = *(const float4*)&wp[c][dq*4];
        red[warpid][lane][c] = s.x*wv.x + s.y*wv.y + s.z*wv.z + s.w*wv.w;
    }
    __syncwarp();
    if (lane < 24){
        float outv = 0.f;
        #pragma unroll 8
        for (int i = 0; i < 32; i++) outv += red[warpid][i][lane];
        g_proj[(size_t)pos*24 + lane] = outv;
    }
}

// ---------------- K3: scan pass 1 — smem-staged proj, paired dirs ----------------
__global__ void __launch_bounds__(128) k_pass1(const float* __restrict__ dtw, const float* __restrict__ dtb,
                                               const float* __restrict__ alog){
    __shared__ __align__(16) float sproj[SEGLEN][12];
    const int s = blockIdx.x, b = blockIdx.y, pair = blockIdx.z;
    const int d = threadIdx.x;
    // cooperative stage of block-uniform proj data (28 pos x 12 floats)
    for (int j = d; j < SEGLEN*12; j += 128){
        int i = j / 12, c = j - i*12;
        sproj[i][c] = g_proj[(size_t)(b*LL + scan_pos(pair, s, i))*24 + pair*12 + c];
    }
    const int kf = pair*2, kb_ = pair*2 + 1;
    float4 wf = *(const float4*)&dtw[(size_t)(kf*128 + d)*4];
    float4 wb = *(const float4*)&dtw[(size_t)(kb_*128 + d)*4];
    float bf = dtb[kf*128 + d], bbs = dtb[kb_*128 + d];
    float Af = -ex2f(alog[kf*128 + d] * LOG2E);
    float Ab = -ex2f(alog[kb_*128 + d] * LOG2E);
    __syncthreads();

    float hf = 0.f, Pf = 1.f;
    float hb = 0.f, Pb = 1.f;
    #pragma unroll 4
    for (int i = 0; i < SEGLEN; i++){
        int bp = b*LL + scan_pos(pair, s, i);
        float xcv = g_xc[(size_t)bp*128 + d];
        float4 f0 = *(const float4*)&sproj[i][0];   // p0f p1f p2f p3f
        float4 f1 = *(const float4*)&sproj[i][4];   // Bf  Cf  p0b p1b
        float4 f2 = *(const float4*)&sproj[i][8];   // p2b p3b Bb  Cb
        // forward
        float xf = fmaf(wf.x, f0.x, bf);
        xf = fmaf(wf.y, f0.y, xf);
        xf = fmaf(wf.z, f0.z, xf);
        xf = fmaf(wf.w, f0.w, xf);
        float uf = sp_u(xf);
        float daf = ex2f(Af * uf);
        float dbf = uf * LN2 * f1.x * xcv;
        hf = fmaf(daf, hf, dbf);
        Pf *= daf;
        // backward (summary in forward order)
        float xb = fmaf(wb.x, f1.z, bbs);
        xb = fmaf(wb.y, f1.w, xb);
        xb = fmaf(wb.z, f2.x, xb);
        xb = fmaf(wb.w, f2.y, xb);
        float ub = sp_u(xb);
        float dab = ex2f(Ab * ub);
        float dbb = ub * LN2 * f2.z * xcv;
        hb = fmaf(dbb, Pb, hb);
        Pb *= dab;
    }
    const int gf = b*4 + kf, gb = b*4 + kb_;
    size_t if_ = ((size_t)gf*NSEG + s)*128 + d;
    size_t ib_ = ((size_t)gb*NSEG + (NSEG-1-s))*128 + d;
    g_hend[if_]  = hf;  g_aprod[if_] = Pf;
    g_hend[ib_]  = hb;  g_aprod[ib_] = Pb;
}

// ---------------- K4: combine (prefix over segments, per scan-chain) ----------------
__global__ void k_comb(){
    const int g = blockIdx.x, d = threadIdx.x;
    float carry = 0.f;
    #pragma unroll 8
    for (int s = 0; s < NSEG; s++){
        size_t idx = ((size_t)g*NSEG + s)*128 + d;
        g_init[idx] = carry;
        carry = fmaf(g_aprod[idx], carry, g_hend[idx]);
    }
}

// ---------------- K5: scan pass 2 — smem-staged proj+xc, both pairs concurrent ----------
__global__ void __launch_bounds__(128) k_pass2(const float* __restrict__ dtw, const float* __restrict__ dtb,
                                               const float* __restrict__ alog, const float* __restrict__ Ds){
    __shared__ __align__(16) float sproj[SEGLEN][12];
    __shared__ float sxc [SEGLEN][128];
    __shared__ float ybuf[SEGLEN][128];
    const int s = blockIdx.x, b = blockIdx.y, pair = blockIdx.z;
    const int d = threadIdx.x;
    for (int j = d; j < SEGLEN*12; j += 128){
        int i = j / 12, c = j - i*12;
        sproj[i][c] = g_proj[(size_t)(b*LL + scan_pos(pair, s, i))*24 + pair*12 + c];
    }
    const int kf = pair*2, kb_ = pair*2 + 1;
    float4 wf = *(const float4*)&dtw[(size_t)(kf*128 + d)*4];
    float4 wb = *(const float4*)&dtw[(size_t)(kb_*128 + d)*4];
    float bf = dtb[kf*128 + d], bbs = dtb[kb_*128 + d];
    float Af = -ex2f(alog[kf*128 + d] * LOG2E);
    float Ab = -ex2f(alog[kb_*128 + d] * LOG2E);
    const int gf = b*4 + kf, gb = b*4 + kb_;
    __syncthreads();

    // backward direction: descending traversal; stash xc in smem
    float hb = g_init[((size_t)gb*NSEG + (NSEG-1-s))*128 + d];
    #pragma unroll 4
    for (int i = SEGLEN-1; i >= 0; i--){
        int bp = b*LL + scan_pos(pair, s, i);
        float xcv = g_xc[(size_t)bp*128 + d];
        sxc[i][d] = xcv;
        float4 f1 = *(const float4*)&sproj[i][4];   // Bf Cf p0b p1b
        float4 f2 = *(const float4*)&sproj[i][8];   // p2b p3b Bb Cb
        float xb = fmaf(wb.x, f1.z, bbs);
        xb = fmaf(wb.y, f1.w, xb);
        xb = fmaf(wb.z, f2.x, xb);
        xb = fmaf(wb.w, f2.y, xb);
        float ub = sp_u(xb);
        float dab = ex2f(Ab * ub);
        float dbb = ub * LN2 * f2.z * xcv;
        hb = fmaf(dab, hb, dbb);
        ybuf[i][d] = hb * f2.w;
    }
    // forward direction + merge (xc from smem, zero global loads)
    float sumDs = Ds[d] + Ds[128+d] + Ds[256+d] + Ds[384+d];
    float hf = g_init[((size_t)gf*NSEG + s)*128 + d];
    #pragma unroll 4
    for (int i = 0; i < SEGLEN; i++){
        int bp = b*LL + scan_pos(pair, s, i);
        float xcv = sxc[i][d];
        float4 f0 = *(const float4*)&sproj[i][0];   // p0f p1f p2f p3f
        float4 f1 = *(const float4*)&sproj[i][4];   // Bf Cf ..
        float xf = fmaf(wf.x, f0.x, bf);
        xf = fmaf(wf.y, f0.y, xf);
        xf = fmaf(wf.z, f0.z, xf);
        xf = fmaf(wf.w, f0.w, xf);
        float uf = sp_u(xf);
        float daf = ex2f(Af * uf);
        float dbf = uf * LN2 * f1.x * xcv;
        hf = fmaf(daf, hf, dbf);
        float val = fmaf(hf, f1.y, ybuf[i][d]);
        if (pair == 0){
            g_ysum[(size_t)bp*128 + d] = fmaf(xcv, sumDs, val);
        } else {
            g_ysum2[(size_t)bp*128 + d] = val;
        }
    }
}

// ---------------- K6: LayerNorm + SiLU gate + spatial mean ----------------
__global__ void __launch_bounds__(256) k_final(const float* __restrict__ nw, const float* __restrict__ nb,
                                               float* __restrict__ out){
    const int b = blockIdx.y;
    const int t = threadIdx.x;
    const int warp = t >> 5, lane = t & 31;
    const int d4 = lane*4;
    float4 w4 = *(const float4*)&nw[d4];
    float4 b4 = *(const float4*)&nb[d4];

    float4 acc = make_float4(0.f,0.f,0.f,0.f);
    #pragma unroll 2
    for (int j = 0; j < 8; j++){
        int p = blockIdx.x*64 + warp*8 + j;
        size_t base = ((size_t)(b*LL + p))*128 + d4;
        float4 v  = *(const float4*)&g_ysum[base];
        float4 v2 = *(const float4*)&g_ysum2[base];
        v.x += v2.x; v.y += v2.y; v.z += v2.z; v.w += v2.w;
        float sm = v.x+v.y+v.z+v.w;
        #pragma unroll
        for (int o = 16; o > 0; o >>= 1) sm += __shfl_xor_sync(~0u, sm, o);
        float mu = sm * (1.f/128.f);
        float4 dv = make_float4(v.x-mu, v.y-mu, v.z-mu, v.w-mu);
        float s2 = dv.x*dv.x + dv.y*dv.y + dv.z*dv.z + dv.w*dv.w;
        #pragma unroll
        for (int o = 16; o > 0; o >>= 1) s2 += __shfl_xor_sync(~0u, s2, o);
        float rstd = rsqrtf(s2 * (1.f/128.f) + 1e-5f);
        float4 z = *(const float4*)&g_xz[((size_t)(b*LL + p))*256 + 128 + d4];
        float gx = z.x*fsigmoid(z.x), gy = z.y*fsigmoid(z.y);
        float gz = z.z*fsigmoid(z.z), gw = z.w*fsigmoid(z.w);
        acc.x = fmaf(fmaf(dv.x*rstd, w4.x, b4.x), gx, acc.x);
        acc.y = fmaf(fmaf(dv.y*rstd, w4.y, b4.y), gy, acc.y);
        acc.z = fmaf(fmaf(dv.z*rstd, w4.z, b4.z), gz, acc.z);
        acc.w = fmaf(fmaf(dv.w*rstd, w4.w, b4.w), gw, acc.w);
    }
    const float sc = 1.f/(float)LL;
    atomicAdd(&out[b*128 + d4 + 0], acc.x*sc);
    atomicAdd(&out[b*128 + d4 + 1], acc.y*sc);
    atomicAdd(&out[b*128 + d4 + 2], acc.z*sc);
    atomicAdd(&out[b*128 + d4 + 3], acc.w*sc);
}

// ---------------- launch ----------------
extern "C" void kernel_launch(void* const* d_in, const int* in_sizes, int n_in,
                              void* d_out, int out_size){
    const float* x    = (const float*)d_in[0];
    const float* inw  = (const float*)d_in[1];
    const float* cw   = (const float*)d_in[2];
    const float* cb   = (const float*)d_in[3];
    const float* xpw  = (const float*)d_in[4];
    const float* dtw  = (const float*)d_in[5];
    const float* dtb  = (const float*)d_in[6];
    const float* alog = (const float*)d_in[7];
    const float* Ds   = (const float*)d_in[8];
    const float* onw  = (const float*)d_in[9];
    const float* onb  = (const float*)d_in[10];
    float* out = (float*)d_out;

    k_zero<<<(BB*DD + 255)/256, 256>>>(out);
    k_gemm<<<dim3((BB*LL)/128, 4), 256>>>(x, inw);
    k_convp<<<(BB*LL)/8, 256>>>(cw, cb, xpw);
    k_pass1<<<dim3(NSEG, BB, 2), 128>>>(dtw, dtb, alog);
    k_comb<<<64, 128>>>();
    k_pass2<<<dim3(NSEG, BB, 2), 128>>>(dtw, dtb, alog, Ds);
    k_final<<<dim3(LL/64, BB), 256>>>(onw, onb, out);
}